// round 10
// baseline (speedup 1.0000x reference)
#include <cuda_runtime.h>
#include <math.h>
#include <stdint.h>

// Problem constants
#define Bz 2
#define Tt 2048
#define Dd 1024
#define Hh 16
#define dh 64
#define INNER 1024
#define Mrows 4096   // B*T
#define NCHUNK 32
#define CP 65        // padded stride for 64x64 smem tiles (SIMT kernels)
#define CO 68        // padded stride for chunk_out mma tiles

// ---------------- scratch ----------------------------------------------------
__device__ float g_Xq[Mrows * INNER];
__device__ float g_Xk[Mrows * INNER];
__device__ float g_Xv[Mrows * INNER];
__device__ float g_Xg[Mrows * INNER];
__device__ float g_Qn[Mrows * INNER];
__device__ float g_Kn[Mrows * INNER];
__device__ float g_Vv[Mrows * INNER];
__device__ float g_AB[Mrows * 32];
__device__ float g_O [Mrows * INNER];
__device__ float g_Y [Mrows * INNER];
__device__ float g_xa[Mrows * Dd];
__device__ float g_Wr[5 * Dd * INNER];   // TRANSPOSED weights: [n][k], tf32-rounded
__device__ float g_T [1024 * 4096];
__device__ float g_W [1024 * 4096];
__device__ float g_M [1024 * 4096];
__device__ float g_N [1024 * 4096];
__device__ float g_S0[1024 * 4096];
__device__ float g_gam[1024 * 64];
__device__ float g_r  [1024 * 64];

// ---------------- helpers ----------------------------------------------------
__device__ __forceinline__ unsigned cvt_tf32(float f) {
    unsigned u;
    asm("cvt.rna.tf32.f32 %0, %1;" : "=r"(u) : "f"(f));
    return u;
}
__device__ __forceinline__ float rna_tf32(float f) {
    return __uint_as_float(cvt_tf32(f));
}
__device__ __forceinline__ uint32_t smem_u32(const void* p) {
    uint32_t a;
    asm("{ .reg .u64 t; cvta.to.shared.u64 t, %1; cvt.u32.u64 %0, t; }"
        : "=r"(a) : "l"(p));
    return a;
}
__device__ __forceinline__ void cp16(uint32_t saddr, const void* gptr) {
    asm volatile("cp.async.cg.shared.global [%0], [%1], 16;" :: "r"(saddr), "l"(gptr));
}
#define CP_COMMIT() asm volatile("cp.async.commit_group;" ::: "memory")

__device__ __forceinline__ void mma_tf32(float* d, unsigned a0, unsigned a1,
                                         unsigned a2, unsigned a3,
                                         unsigned b0, unsigned b1) {
    asm("mma.sync.aligned.m16n8k8.row.col.f32.tf32.tf32.f32 "
        "{%0,%1,%2,%3}, {%4,%5,%6,%7}, {%8,%9}, {%0,%1,%2,%3};\n"
        : "+f"(d[0]), "+f"(d[1]), "+f"(d[2]), "+f"(d[3])
        : "r"(a0), "r"(a1), "r"(a2), "r"(a3), "r"(b0), "r"(b1));
}

#define LDMX4(r0, r1, r2, r3, addr) \
    asm volatile("ldmatrix.sync.aligned.m8n8.x4.shared.b16 {%0,%1,%2,%3}, [%4];" \
        : "=r"(r0), "=r"(r1), "=r"(r2), "=r"(r3) : "r"(addr))

// ---------------- tf32 GEMM, 128x128 tile, ldmatrix fragments ----------------
// A (M,1024) row-major pre-rounded. Bt = W^T (N,1024) row-major (n-major!).
#define GP 20                       // padded stride (floats) for A and B tiles
#define TST (128 * GP)              // floats per stage per operand (2560)
#define GSMEM (6 * TST * 4)         // 61440 bytes

__device__ __forceinline__ void tgemm128(const float* __restrict__ A,
                                         const float* __restrict__ Bt,
                                         float* __restrict__ C,
                                         int N, int bm, int bn,
                                         bool do_silu)
{
    extern __shared__ float smp[];

    const int tid  = threadIdx.x;
    const int lane = tid & 31;
    const int wid  = tid >> 5;
    const int warpM = (wid & 1) * 64;
    const int warpN = (wid >> 1) * 64;

    float acc[4][8][4];
#pragma unroll
    for (int mt = 0; mt < 4; mt++)
#pragma unroll
        for (int nt = 0; nt < 8; nt++)
#pragma unroll
            for (int i = 0; i < 4; i++) acc[mt][nt][i] = 0.f;

    const uint32_t asu = smem_u32(smp);
    const uint32_t bsu = asu + 3 * TST * 4;

    const int lrow = tid >> 2;
    const int lkq  = (tid & 3) << 2;

    auto load_stage = [&](int kt, int st) {
        const int k0 = kt << 4;
        const uint32_t sa = asu + st * (TST * 4);
        const uint32_t sb = bsu + st * (TST * 4);
#pragma unroll
        for (int i = 0; i < 4; i++) {
            const int row = lrow + i * 32;
            cp16(sa + (row * GP + lkq) * 4, A  + (long)(bm + row) * 1024 + k0 + lkq);
            cp16(sb + (row * GP + lkq) * 4, Bt + (long)(bn + row) * 1024 + k0 + lkq);
        }
        CP_COMMIT();
    };

    // per-lane ldmatrix offset: tile t = lane>>3; row (lane&7)+8*(t&1); k-half t>>1
    const int lt = lane >> 3;
    const uint32_t lmo = ((((lt & 1) * 8 + (lane & 7)) * GP + (lt >> 1) * 4)) * 4;

    load_stage(0, 0);
    load_stage(1, 1);
    load_stage(2, 2);

    for (int kt = 0; kt < 64; kt++) {
        const int st = kt - (kt / 3) * 3;
        if (kt <= 61)      asm volatile("cp.async.wait_group 2;" ::: "memory");
        else if (kt == 62) asm volatile("cp.async.wait_group 1;" ::: "memory");
        else               asm volatile("cp.async.wait_group 0;" ::: "memory");
        __syncthreads();

        const uint32_t sa = asu + st * (TST * 4) + lmo;
        const uint32_t sb = bsu + st * (TST * 4) + lmo;
#pragma unroll
        for (int k8 = 0; k8 < 16; k8 += 8) {
            unsigned af[4][4], bf[8][2];
#pragma unroll
            for (int mt = 0; mt < 4; mt++)
                LDMX4(af[mt][0], af[mt][1], af[mt][2], af[mt][3],
                      sa + ((warpM + mt * 16) * GP + k8) * 4);
#pragma unroll
            for (int np = 0; np < 4; np++)
                LDMX4(bf[2 * np][0], bf[2 * np + 1][0], bf[2 * np][1], bf[2 * np + 1][1],
                      sb + ((warpN + np * 16) * GP + k8) * 4);
#pragma unroll
            for (int mt = 0; mt < 4; mt++)
#pragma unroll
                for (int nt = 0; nt < 8; nt++)
                    mma_tf32(acc[mt][nt], af[mt][0], af[mt][1], af[mt][2], af[mt][3],
                             bf[nt][0], bf[nt][1]);
        }
        __syncthreads();
        if (kt + 3 < 64) load_stage(kt + 3, st);
    }

#pragma unroll
    for (int mt = 0; mt < 4; mt++) {
        const int r0 = bm + warpM + mt * 16 + (lane >> 2);
#pragma unroll
        for (int nt = 0; nt < 8; nt++) {
            const int c = bn + warpN + nt * 8 + ((lane & 3) << 1);
            float v0 = acc[mt][nt][0], v1 = acc[mt][nt][1];
            float v2 = acc[mt][nt][2], v3 = acc[mt][nt][3];
            if (do_silu) {
                v0 = v0 / (1.f + expf(-v0));
                v1 = v1 / (1.f + expf(-v1));
                v2 = v2 / (1.f + expf(-v2));
                v3 = v3 / (1.f + expf(-v3));
            }
            *(float2*)(C + (long)r0 * N + c)       = make_float2(v0, v1);
            *(float2*)(C + (long)(r0 + 8) * N + c) = make_float2(v2, v3);
        }
    }
}

__global__ __launch_bounds__(128) void proj_gemm_kernel()
{
    const int z = blockIdx.z;
    const float* W = g_Wr + (long)z * (Dd * INNER);
    float* O;
    bool silu = false;
    switch (z) {
        case 0:  O = g_Xq; break;
        case 1:  O = g_Xk; break;
        case 2:  O = g_Xv; break;
        default: O = g_Xg; silu = true; break;
    }
    tgemm128(g_xa, W, O, INNER, blockIdx.y * 128, blockIdx.x * 128, silu);
}

__global__ __launch_bounds__(128) void out_gemm_kernel(float* __restrict__ out)
{
    tgemm128(g_Y, g_Wr + 4L * Dd * INNER, out, Dd,
             blockIdx.y * 128, blockIdx.x * 128, false);
}

// ---------------- pre-passes -------------------------------------------------
__global__ __launch_bounds__(256) void cvt_kernel(const float* __restrict__ x)
{
    const long i = ((long)blockIdx.x * 256 + threadIdx.x) * 4;
    float4 v = *(const float4*)(x + i);
    v.x = rna_tf32(v.x); v.y = rna_tf32(v.y);
    v.z = rna_tf32(v.z); v.w = rna_tf32(v.w);
    *(float4*)(g_xa + i) = v;
}

// transpose + rna: W (k-major 1024x1024) -> g_Wr slice (n-major)
__global__ __launch_bounds__(256) void wtrans_kernel(
    const float* __restrict__ Wq, const float* __restrict__ Wk,
    const float* __restrict__ Wv, const float* __restrict__ Wg,
    const float* __restrict__ Wo)
{
    const float* W;
    switch (blockIdx.z) {
        case 0: W = Wq; break;
        case 1: W = Wk; break;
        case 2: W = Wv; break;
        case 3: W = Wg; break;
        default: W = Wo; break;
    }
    float* Out = g_Wr + (long)blockIdx.z * (Dd * INNER);
    __shared__ float t[32][33];
    const int tx = threadIdx.x & 31;
    const int ty = threadIdx.x >> 5;
    const int bx = blockIdx.x * 32;    // n block
    const int by = blockIdx.y * 32;    // k block
#pragma unroll
    for (int i = 0; i < 4; i++)
        t[ty + i * 8][tx] = W[(long)(by + ty + i * 8) * 1024 + bx + tx];
    __syncthreads();
#pragma unroll
    for (int i = 0; i < 4; i++)
        Out[(long)(bx + ty + i * 8) * 1024 + by + tx] = rna_tf32(t[tx][ty + i * 8]);
}

// ---------------- conv (z<3) + alpha/beta mini-GEMM (z==3) -------------------
__global__ __launch_bounds__(128) void convab_kernel(
    const float* __restrict__ x,
    const float* __restrict__ cq_w, const float* __restrict__ cq_b,
    const float* __restrict__ ck_w, const float* __restrict__ ck_b,
    const float* __restrict__ cv_w, const float* __restrict__ cv_b,
    const float* __restrict__ Wa, const float* __restrict__ ba,
    const float* __restrict__ Wb, const float* __restrict__ bb)
{
    __shared__ float s_ab[32 * 65 + 64 * 33];

    if (blockIdx.z == 3) {
        if (blockIdx.x >= 128 || blockIdx.y != 0) return;
        const int blk = blockIdx.x;
        const int tid = threadIdx.x;
        float* xs = s_ab;
        float* ws = s_ab + 32 * 65;
        const int mrow = tid >> 2;
        const int ogrp = tid & 3;

        float acc[8];
#pragma unroll
        for (int j = 0; j < 8; j++) acc[j] = 0.f;

        for (int k0 = 0; k0 < Dd; k0 += 64) {
#pragma unroll
            for (int i = 0; i < 4; i++) {
                const int idx = tid + i * 128;
                const int row = idx >> 4;
                const int c4  = (idx & 15) << 2;
                float4 v = *(const float4*)(x + (long)(blk * 32 + row) * Dd + k0 + c4);
                xs[row * 65 + c4 + 0] = v.x;
                xs[row * 65 + c4 + 1] = v.y;
                xs[row * 65 + c4 + 2] = v.z;
                xs[row * 65 + c4 + 3] = v.w;
            }
#pragma unroll
            for (int i = 0; i < 16; i++) {
                const int idx = tid + i * 128;
                const int row = idx >> 5;
                const int col = idx & 31;
                ws[row * 33 + col] = (col < 16) ? Wa[(k0 + row) * Hh + col]
                                                : Wb[(k0 + row) * Hh + col - 16];
            }
            __syncthreads();
#pragma unroll 8
            for (int k = 0; k < 64; k++) {
                const float xv = xs[mrow * 65 + k];
#pragma unroll
                for (int j = 0; j < 8; j++)
                    acc[j] = fmaf(xv, ws[k * 33 + ogrp * 8 + j], acc[j]);
            }
            __syncthreads();
        }
#pragma unroll
        for (int j = 0; j < 8; j++) {
            const int o = ogrp * 8 + j;
            const float bias = (o < 16) ? ba[o] : bb[o - 16];
            g_AB[(long)(blk * 32 + mrow) * 32 + o] =
                1.f / (1.f + expf(-(acc[j] + bias)));
        }
        return;
    }

    const float* Xin; float* Out; const float* cw; const float* cb; bool donorm;
    switch (blockIdx.z) {
        case 0:  Xin = g_Xq; Out = g_Qn; cw = cq_w; cb = cq_b; donorm = true;  break;
        case 1:  Xin = g_Xk; Out = g_Kn; cw = ck_w; cb = ck_b; donorm = true;  break;
        default: Xin = g_Xv; Out = g_Vv; cw = cv_w; cb = cv_b; donorm = false; break;
    }
    const int bt0 = blockIdx.x * 16;
    const int t0  = bt0 & (Tt - 1);
    const int lane = threadIdx.x & 31;
    const int wid  = threadIdx.x >> 5;
    const int h = blockIdx.y * 4 + wid;
    const int c0 = h * 64 + lane;

    float x0[19], x1[19];
#pragma unroll
    for (int i = 0; i < 19; i++) {
        const int t = t0 - 3 + i;
        if (t < 0) { x0[i] = 0.f; x1[i] = 0.f; }
        else {
            const long g = (long)(bt0 - t0 + t) * INNER + c0;
            x0[i] = Xin[g];
            x1[i] = Xin[g + 32];
        }
    }
    float w0[4], w1[4];
#pragma unroll
    for (int k = 0; k < 4; k++) {
        w0[k] = cw[c0 * 4 + k];
        w1[k] = cw[(c0 + 32) * 4 + k];
    }
    const float b0 = cb[c0], b1 = cb[c0 + 32];

#pragma unroll
    for (int tt = 0; tt < 16; tt++) {
        float a0 = b0, a1 = b1;
#pragma unroll
        for (int k = 0; k < 4; k++) {
            a0 = fmaf(x0[tt + k], w0[k], a0);
            a1 = fmaf(x1[tt + k], w1[k], a1);
        }
        float s0 = a0 / (1.f + expf(-a0));
        float s1 = a1 / (1.f + expf(-a1));
        float ss = s0 * s0 + s1 * s1;
        ss += __shfl_xor_sync(0xffffffffu, ss, 16);
        ss += __shfl_xor_sync(0xffffffffu, ss, 8);
        ss += __shfl_xor_sync(0xffffffffu, ss, 4);
        ss += __shfl_xor_sync(0xffffffffu, ss, 2);
        ss += __shfl_xor_sync(0xffffffffu, ss, 1);
        if (donorm) {
            const float inv = 1.f / fmaxf(sqrtf(ss), 1e-12f);
            s0 *= inv; s1 *= inv;
        }
        const long g = (long)(bt0 + tt) * INNER + c0;
        Out[g] = s0;
        Out[g + 32] = s1;
    }
}

// ============== chunked delta-rule scan ======================================

__global__ __launch_bounds__(256, 2) void chunk_prep_kernel()
{
    extern __shared__ float sm[];
    float* sK = sm;
    float* sV = sm + 64 * CP;
    float* sL = sm + 2 * 64 * CP;
    float* sGam = sm + 3 * 64 * CP;
    float* sR   = sGam + 64;

    const int chunk = blockIdx.x;
    const int c  = chunk & (NCHUNK - 1);
    const int bh = chunk >> 5;
    const int b = bh >> 4, h = bh & 15;
    const int tid = threadIdx.x;
    const long rowbase = (long)b * Tt + c * 64;
    const int colbase = h * dh;
    const long cb = (long)chunk * 4096;

    for (int idx = tid; idx < 1024; idx += 256) {
        const int row = idx >> 4;
        const int c4  = (idx & 15) << 2;
        const long g = (rowbase + row) * INNER + colbase + c4;
        float4 kv = *(const float4*)(g_Kn + g);
        float4 vv = *(const float4*)(g_Vv + g);
        sK[row * CP + c4 + 0] = kv.x; sK[row * CP + c4 + 1] = kv.y;
        sK[row * CP + c4 + 2] = kv.z; sK[row * CP + c4 + 3] = kv.w;
        sV[row * CP + c4 + 0] = vv.x; sV[row * CP + c4 + 1] = vv.y;
        sV[row * CP + c4 + 2] = vv.z; sV[row * CP + c4 + 3] = vv.w;
    }
    if (tid < 64) {
        sGam[tid] = g_AB[(rowbase + tid) * 32 + h];
        sR[tid]   = g_AB[(rowbase + tid) * 32 + 16 + h];
    }
    __syncthreads();
    if (tid == 0) {
        float p = 1.f;
        for (int i = 0; i < 64; i++) { p *= sGam[i]; sGam[i] = p; }
    }
    __syncthreads();
    if (tid < 64) sR[tid] = sR[tid] / sGam[tid];
    __syncthreads();

    const int ty = tid >> 4, tx = tid & 15;

    {
        float acc[4][4];
#pragma unroll
        for (int v = 0; v < 4; v++)
#pragma unroll
            for (int u = 0; u < 4; u++) acc[v][u] = 0.f;
        for (int k = 0; k < 64; k++) {
            float a[4], bb[4];
#pragma unroll
            for (int v = 0; v < 4; v++) a[v]  = sK[(ty + 16 * v) * CP + k];
#pragma unroll
            for (int u = 0; u < 4; u++) bb[u] = sK[(tx + 16 * u) * CP + k];
#pragma unroll
            for (int v = 0; v < 4; v++)
#pragma unroll
                for (int u = 0; u < 4; u++)
                    acc[v][u] = fmaf(a[v], bb[u], acc[v][u]);
        }
#pragma unroll
        for (int v = 0; v < 4; v++)
#pragma unroll
            for (int u = 0; u < 4; u++) {
                const int j = ty + 16 * v, i = tx + 16 * u;
                sL[j * CP + i] = (i < j) ? acc[v][u] * sGam[j] * sR[i] : 0.f;
            }
        __syncthreads();
    }

    float rr_[64];
    const int col = tid & 63;
    const int isW = (tid >> 6) & 1;
    if (tid < 128) {
#pragma unroll
        for (int j = 0; j < 64; j++)
            rr_[j] = isW ? sGam[j] * sK[j * CP + col] : sV[j * CP + col];
#pragma unroll
        for (int j = 0; j < 64; j++) {
            const float xj = rr_[j];
#pragma unroll
            for (int i = j + 1; i < 64; i++)
                rr_[i] -= sL[i * CP + j] * xj;
        }
    }
    __syncthreads();

    const float gC = sGam[63];
    if (tid < 128) {
        float* dst  = isW ? sL : sV;
        float* gdst = isW ? g_W : g_T;
#pragma unroll
        for (int j = 0; j < 64; j++) {
            dst[j * CP + col] = rr_[j];
            gdst[cb + j * 64 + col] = rr_[j];
        }
    } else {
        const int t2 = tid - 128;
        for (int idx = t2; idx < 4096; idx += 128) {
            const int j = idx >> 6;
            sK[j * CP + (idx & 63)] *= gC * sR[j];
        }
    }
    if (tid < 64) {
        g_gam[chunk * 64 + tid] = sGam[tid];
        g_r  [chunk * 64 + tid] = sR[tid];
    }
    __syncthreads();

    {
        float am[4][4], an[4][4];
#pragma unroll
        for (int v = 0; v < 4; v++)
#pragma unroll
            for (int u = 0; u < 4; u++) {
                am[v][u] = ((ty == tx) && (v == u)) ? gC : 0.f;
                an[v][u] = 0.f;
            }
        for (int j = 0; j < 64; j++) {
            float wv[4], tv[4], kb[4];
#pragma unroll
            for (int v = 0; v < 4; v++) {
                wv[v] = sL[j * CP + ty + 16 * v];
                tv[v] = sV[j * CP + ty + 16 * v];
            }
#pragma unroll
            for (int u = 0; u < 4; u++) kb[u] = sK[j * CP + tx + 16 * u];
#pragma unroll
            for (int v = 0; v < 4; v++)
#pragma unroll
                for (int u = 0; u < 4; u++) {
                    am[v][u] = fmaf(-wv[v], kb[u], am[v][u]);
                    an[v][u] = fmaf( tv[v], kb[u], an[v][u]);
                }
        }
#pragma unroll
        for (int v = 0; v < 4; v++)
#pragma unroll
            for (int u = 0; u < 4; u++) {
                const int p = ty + 16 * v, q = tx + 16 * u;
                g_M[cb + p * 64 + q] = am[v][u];
                g_N[cb + p * 64 + q] = an[v][u];
            }
    }
}

__global__ __launch_bounds__(256) void chunk_scan_kernel()
{
    __shared__ float sS[16 * 64];
    __shared__ float sM[64 * 64];
    const int bh = blockIdx.x;
    const int R0 = blockIdx.y * 16;
    const int tid = threadIdx.x;
    const int row = tid >> 4;
    const int tx  = tid & 15;

    for (int idx = tid; idx < 1024; idx += 256) sS[idx] = 0.f;
    __syncthreads();

    for (int c = 0; c < NCHUNK; c++) {
        const long cb = (long)(bh * NCHUNK + c) * 4096;
        for (int idx = tid; idx < 1024; idx += 256)
            g_S0[cb + (long)(R0 + (idx >> 6)) * 64 + (idx & 63)] = sS[idx];
        for (int idx = tid; idx < 4096; idx += 256)
            sM[idx] = g_M[cb + idx];
        __syncthreads();

        float acc[4];
#pragma unroll
        for (int u = 0; u < 4; u++)
            acc[u] = g_N[cb + (long)(R0 + row) * 64 + tx + 16 * u];
        for (int k = 0; k < 64; k++) {
            const float s = sS[row * 64 + k];
#pragma unroll
            for (int u = 0; u < 4; u++)
                acc[u] = fmaf(s, sM[k * 64 + tx + 16 * u], acc[u]);
        }
        __syncthreads();
#pragma unroll
        for (int u = 0; u < 4; u++) sS[row * 64 + tx + 16 * u] = acc[u];
        __syncthreads();
    }
}

// ---- chunk_out: tensor-core (tf32 mma) version ------------------------------
#define CO_SMEM ((6 * 64 * CO + 128) * 4)

__device__ __forceinline__ void mma_block64(const float* __restrict__ As_,
                                            const float* __restrict__ Bs_,
                                            int m0, int n0, int lane,
                                            float acc[2][2][4])
{
#pragma unroll
    for (int k8 = 0; k8 < 64; k8 += 8) {
        const int kk0 = k8 + (lane & 3);
        const int kk1 = kk0 + 4;
        unsigned af[2][4], bf[2][2];
#pragma unroll
        for (int mt = 0; mt < 2; mt++) {
            const int r0 = m0 + mt * 16 + (lane >> 2);
            af[mt][0] = __float_as_uint(As_[r0 * CO + kk0]);
            af[mt][1] = __float_as_uint(As_[(r0 + 8) * CO + kk0]);
            af[mt][2] = __float_as_uint(As_[r0 * CO + kk1]);
            af[mt][3] = __float_as_uint(As_[(r0 + 8) * CO + kk1]);
        }
#pragma unroll
        for (int nt = 0; nt < 2; nt++) {
            const int n = n0 + nt * 8 + (lane >> 2);
            bf[nt][0] = __float_as_uint(Bs_[n * CO + kk0]);
            bf[nt][1] = __float_as_uint(Bs_[n * CO + kk1]);
        }
#pragma unroll
        for (int mt = 0; mt < 2; mt++)
#pragma unroll
            for (int nt = 0; nt < 2; nt++)
                mma_tf32(acc[mt][nt], af[mt][0], af[mt][1], af[mt][2], af[mt][3],
                         bf[nt][0], bf[nt][1]);
    }
}

__global__ __launch_bounds__(256, 2) void chunk_out_kernel()
{
    extern __shared__ float sm[];
    float* sQg = sm;
    float* sK  = sm + 64 * CO;
    float* sS0 = sm + 2 * 64 * CO;
    float* sW  = sm + 3 * 64 * CO;
    float* sT  = sm + 4 * 64 * CO;
    float* sA  = sm + 5 * 64 * CO;
    float* sGam = sm + 6 * 64 * CO;
    float* sR   = sGam + 64;
    float* sUT  = sK;

    const int chunk = blockIdx.x;
    const int c  = chunk & (NCHUNK - 1);
    const int bh = chunk >> 5;
    const int b = bh >> 4, h = bh & 15;
    const int tid = threadIdx.x;
    const int lane = tid & 31;
    const int wid  = tid >> 5;
    const int m0 = (wid & 1) * 32;
    const int n0 = (wid >> 1) * 16;
    const long rowbase = (long)b * Tt + c * 64;
    const int colbase = h * dh;
    const long cb = (long)chunk * 4096;

    if (tid < 64) {
        sGam[tid] = g_gam[chunk * 64 + tid];
        sR[tid]   = g_r[chunk * 64 + tid];
    }
    __syncthreads();

    for (int idx = tid; idx < 1024; idx += 256) {
        const int row = idx >> 4;
        const int c4  = (idx & 15) << 2;
        const long g = (rowbase + row) * INNER + colbase + c4;
        float4 qv = *(const float4*)(g_Qn + g);
        float4 kv = *(const float4*)(g_Kn + g);
        const float gm = sGam[row];
        sQg[row * CO + c4 + 0] = rna_tf32(qv.x * gm);
        sQg[row * CO + c4 + 1] = rna_tf32(qv.y * gm);
        sQg[row * CO + c4 + 2] = rna_tf32(qv.z * gm);
        sQg[row * CO + c4 + 3] = rna_tf32(qv.w * gm);
        sK [row * CO + c4 + 0] = rna_tf32(kv.x);
        sK [row * CO + c4 + 1] = rna_tf32(kv.y);
        sK [row * CO + c4 + 2] = rna_tf32(kv.z);
        sK [row * CO + c4 + 3] = rna_tf32(kv.w);
    }
    for (int idx = tid; idx < 4096; idx += 256) {
        const int r = idx >> 6, cc = idx & 63;
        sS0[r * CO + cc] = rna_tf32(g_S0[cb + idx]);
        sW [r * CO + cc] = rna_tf32(g_W[cb + idx]);
        sT [r * CO + cc] = g_T[cb + idx];
    }
    __syncthreads();

    // Phase 1: A = tril(diag(gam) Q K^T diag(r))
    {
        float acc[2][2][4];
#pragma unroll
        for (int mt = 0; mt < 2; mt++)
#pragma unroll
            for (int nt = 0; nt < 2; nt++)
#pragma unroll
                for (int i = 0; i < 4; i++) acc[mt][nt][i] = 0.f;
        mma_block64(sQg, sK, m0, n0, lane, acc);
        __syncthreads();
#pragma unroll
        for (int mt = 0; mt < 2; mt++) {
            const int t0r = m0 + mt * 16 + (lane >> 2);
#pragma unroll
            for (int nt = 0; nt < 2; nt++) {
                const int j0 = n0 + nt * 8 + ((lane & 3) << 1);
#pragma unroll
                for (int half = 0; half < 2; half++) {
                    const int t = t0r + half * 8;
                    const float v0 = acc[mt][nt][half * 2 + 0];
                    const float v1 = acc[mt][nt][half * 2 + 1];
                    sA[t * CO + j0]     = (j0     <= t) ? rna_tf32(v0 * sR[j0])     : 0.f;
                    sA[t * CO + j0 + 1] = (j0 + 1 <= t) ? rna_tf32(v1 * sR[j0 + 1]) : 0.f;
                }
            }
        }
    }

    // Phase 2: UT[a][j] = T[j][a] - (S0 W^T)(a,j)
    {
        float acc[2][2][4];
#pragma unroll
        for (int mt = 0; mt < 2; mt++)
#pragma unroll
            for (int nt = 0; nt < 2; nt++)
#pragma unroll
                for (int i = 0; i < 4; i++) acc[mt][nt][i] = 0.f;
        mma_block64(sS0, sW, m0, n0, lane, acc);
        __syncthreads();
#pragma unroll
        for (int mt = 0; mt < 2; mt++) {
            const int a0 = m0 + mt * 16 + (lane >> 2);
#pragma unroll
            for (int nt = 0; nt < 2; nt++) {
                const int j0 = n0 + nt * 8 + ((lane & 3) << 1);
#pragma unroll
                for (int half = 0; half < 2; half++) {
                    const int a = a0 + half * 8;
                    sUT[a * CO + j0]     = rna_tf32(sT[j0 * CO + a]       - acc[mt][nt][half * 2 + 0]);
                    sUT[a * CO + j0 + 1] = rna_tf32(sT[(j0 + 1) * CO + a] - acc[mt][nt][half * 2 + 1]);
                }
            }
        }
    }
    __syncthreads();

    // Phase 3: O = Qg S0^T + A U
    {
        float acc[2][2][4];
#pragma unroll
        for (int mt = 0; mt < 2; mt++)
#pragma unroll
            for (int nt = 0; nt < 2; nt++)
#pragma unroll
                for (int i = 0; i < 4; i++) acc[mt][nt][i] = 0.f;
        mma_block64(sQg, sS0, m0, n0, lane, acc);
        mma_block64(sA, sUT, m0, n0, lane, acc);
#pragma unroll
        for (int mt = 0; mt < 2; mt++) {
            const int t0r = m0 + mt * 16 + (lane >> 2);
#pragma unroll
            for (int nt = 0; nt < 2; nt++) {
                const int a0 = n0 + nt * 8 + ((lane & 3) << 1);
#pragma unroll
                for (int half = 0; half < 2; half++) {
                    const int t = t0r + half * 8;
                    *(float2*)(g_O + (rowbase + t) * INNER + colbase + a0) =
                        make_float2(acc[mt][nt][half * 2 + 0],
                                    acc[mt][nt][half * 2 + 1]);
                }
            }
        }
    }
}

// ---------------- RMS norm + (1+gamma) + gate (float4) -----------------------
__global__ __launch_bounds__(256) void rmsgate_kernel(const float* __restrict__ gamma)
{
    const int m = blockIdx.x;
    const int tid = threadIdx.x;
    const long base = (long)m * INNER + tid * 4;
    float4 xv = *(const float4*)(g_O + base);
    float ss = xv.x * xv.x + xv.y * xv.y + xv.z * xv.z + xv.w * xv.w;
    for (int off = 16; off; off >>= 1) ss += __shfl_xor_sync(0xffffffffu, ss, off);
    __shared__ float red[8];
    if ((tid & 31) == 0) red[tid >> 5] = ss;
    __syncthreads();
    float tot = 0.f;
#pragma unroll
    for (int w = 0; w < 8; w++) tot += red[w];
    const float inv = 1.f / sqrtf(tot * (1.f / (float)INNER) + 1e-6f);
    float4 gv = *(const float4*)(g_Xg + base);
    float4 gm = *(const float4*)(gamma + tid * 4);
    float4 o;
    o.x = rna_tf32(xv.x * inv * (1.f + gm.x) * gv.x);
    o.y = rna_tf32(xv.y * inv * (1.f + gm.y) * gv.y);
    o.z = rna_tf32(xv.z * inv * (1.f + gm.z) * gv.z);
    o.w = rna_tf32(xv.w * inv * (1.f + gm.w) * gv.w);
    *(float4*)(g_Y + base) = o;
}

// ---------------- launch -----------------------------------------------------
extern "C" void kernel_launch(void* const* d_in, const int* in_sizes, int n_in,
                              void* d_out, int out_size)
{
    const float* x    = (const float*)d_in[0];
    const float* Wq   = (const float*)d_in[1];
    const float* Wk   = (const float*)d_in[2];
    const float* Wv   = (const float*)d_in[3];
    const float* Wa   = (const float*)d_in[4];
    const float* ba   = (const float*)d_in[5];
    const float* Wb   = (const float*)d_in[6];
    const float* bb   = (const float*)d_in[7];
    const float* Wg   = (const float*)d_in[8];
    const float* Wo   = (const float*)d_in[9];
    const float* cq_w = (const float*)d_in[10];
    const float* cq_b = (const float*)d_in[11];
    const float* ck_w = (const float*)d_in[12];
    const float* ck_b = (const float*)d_in[13];
    const float* cv_w = (const float*)d_in[14];
    const float* cv_b = (const float*)d_in[15];
    const float* gamma= (const float*)d_in[16];
    float* out = (float*)d_out;

    const int prep_smem = (3 * 64 * CP + 128) * sizeof(float);
    cudaFuncSetAttribute(chunk_prep_kernel,
                         cudaFuncAttributeMaxDynamicSharedMemorySize, prep_smem);
    cudaFuncSetAttribute(chunk_out_kernel,
                         cudaFuncAttributeMaxDynamicSharedMemorySize, CO_SMEM);
    cudaFuncSetAttribute(proj_gemm_kernel,
                         cudaFuncAttributeMaxDynamicSharedMemorySize, GSMEM);
    cudaFuncSetAttribute(out_gemm_kernel,
                         cudaFuncAttributeMaxDynamicSharedMemorySize, GSMEM);

    cvt_kernel<<<Mrows * Dd / 1024, 256>>>(x);
    wtrans_kernel<<<dim3(32, 32, 5), 256>>>(Wq, Wk, Wv, Wg, Wo);
    proj_gemm_kernel<<<dim3(INNER / 128, Mrows / 128, 4), 128, GSMEM>>>();
    convab_kernel<<<dim3(Mrows / 16, 4, 4), 128>>>(x, cq_w, cq_b, ck_w, ck_b,
                                                   cv_w, cv_b, Wa, ba, Wb, bb);
    chunk_prep_kernel<<<1024, 256, prep_smem>>>();
    chunk_scan_kernel<<<dim3(Bz * Hh, 4), 256>>>();
    chunk_out_kernel<<<1024, 256, CO_SMEM>>>();
    rmsgate_kernel<<<Mrows, 256>>>(gamma);
    out_gemm_kernel<<<dim3(Dd / 128, Mrows / 128), 128, GSMEM>>>(out);
}

// round 11
// speedup vs baseline: 1.1688x; 1.1688x over previous
#include <cuda_runtime.h>
#include <cuda_fp16.h>
#include <math.h>
#include <stdint.h>

// Problem constants
#define Bz 2
#define Tt 2048
#define Dd 1024
#define Hh 16
#define dh 64
#define INNER 1024
#define Mrows 4096   // B*T
#define NCHUNK 32
#define CP 65        // padded stride for 64x64 smem tiles (SIMT kernels)
#define CO 68        // padded stride for chunk_out mma tiles

// ---------------- scratch ----------------------------------------------------
__device__ float g_Xq[Mrows * INNER];
__device__ float g_Xk[Mrows * INNER];
__device__ float g_Xv[Mrows * INNER];
__device__ float g_Xg[Mrows * INNER];
__device__ float g_Qn[Mrows * INNER];
__device__ float g_Kn[Mrows * INNER];
__device__ float g_Vv[Mrows * INNER];
__device__ float g_AB[Mrows * 32];
__device__ float g_O [Mrows * INNER];
__device__ __half g_xh[Mrows * Dd];        // fp16 x
__device__ __half g_Wh[5 * Dd * INNER];    // fp16 TRANSPOSED weights [n][k]
__device__ __half g_Yh[Mrows * INNER];     // fp16 rms*gamma*gate
__device__ float g_T [1024 * 4096];
__device__ float g_W [1024 * 4096];
__device__ float g_M [1024 * 4096];
__device__ float g_N [1024 * 4096];
__device__ float g_S0[1024 * 4096];
__device__ float g_gam[1024 * 64];
__device__ float g_r  [1024 * 64];

// ---------------- helpers ----------------------------------------------------
__device__ __forceinline__ unsigned cvt_tf32(float f) {
    unsigned u;
    asm("cvt.rna.tf32.f32 %0, %1;" : "=r"(u) : "f"(f));
    return u;
}
__device__ __forceinline__ float rna_tf32(float f) {
    return __uint_as_float(cvt_tf32(f));
}
__device__ __forceinline__ uint32_t smem_u32(const void* p) {
    uint32_t a;
    asm("{ .reg .u64 t; cvta.to.shared.u64 t, %1; cvt.u32.u64 %0, t; }"
        : "=r"(a) : "l"(p));
    return a;
}
__device__ __forceinline__ void cp16(uint32_t saddr, const void* gptr) {
    asm volatile("cp.async.cg.shared.global [%0], [%1], 16;" :: "r"(saddr), "l"(gptr));
}
#define CP_COMMIT() asm volatile("cp.async.commit_group;" ::: "memory")

__device__ __forceinline__ void mma_tf32(float* d, unsigned a0, unsigned a1,
                                         unsigned a2, unsigned a3,
                                         unsigned b0, unsigned b1) {
    asm("mma.sync.aligned.m16n8k8.row.col.f32.tf32.tf32.f32 "
        "{%0,%1,%2,%3}, {%4,%5,%6,%7}, {%8,%9}, {%0,%1,%2,%3};\n"
        : "+f"(d[0]), "+f"(d[1]), "+f"(d[2]), "+f"(d[3])
        : "r"(a0), "r"(a1), "r"(a2), "r"(a3), "r"(b0), "r"(b1));
}

__device__ __forceinline__ void mma_f16(float* d, unsigned a0, unsigned a1,
                                        unsigned a2, unsigned a3,
                                        unsigned b0, unsigned b1) {
    asm("mma.sync.aligned.m16n8k16.row.col.f32.f16.f16.f32 "
        "{%0,%1,%2,%3}, {%4,%5,%6,%7}, {%8,%9}, {%0,%1,%2,%3};\n"
        : "+f"(d[0]), "+f"(d[1]), "+f"(d[2]), "+f"(d[3])
        : "r"(a0), "r"(a1), "r"(a2), "r"(a3), "r"(b0), "r"(b1));
}

// ---------------- fp16 GEMM, 128x128 tile, cp.async 3-stage pipeline ---------
// A (M,1024) row-major fp16. Bt = W^T (N,1024) row-major (n-major) fp16.
#define PADH 24                       // halfs per row (48B; stride 12 words)
#define HST (128 * PADH)              // halfs per stage per operand (3072)
#define GSMEM (6 * HST * 2)           // bytes (36864)

__device__ __forceinline__ void hgemm128(const __half* __restrict__ A,
                                         const __half* __restrict__ Bt,
                                         float* __restrict__ C,
                                         int N, int bm, int bn,
                                         bool do_silu)
{
    extern __shared__ __half smh[];

    const int tid  = threadIdx.x;
    const int lane = tid & 31;
    const int wid  = tid >> 5;
    const int warpM = (wid & 1) * 64;
    const int warpN = (wid >> 1) * 64;

    float acc[4][8][4];
#pragma unroll
    for (int mt = 0; mt < 4; mt++)
#pragma unroll
        for (int nt = 0; nt < 8; nt++)
#pragma unroll
            for (int i = 0; i < 4; i++) acc[mt][nt][i] = 0.f;

    const uint32_t asu = smem_u32(smh);
    const uint32_t bsu = asu + 3 * HST * 2;

    auto load_stage = [&](int kt, int st) {
        const int k0 = kt << 4;
        const uint32_t sa = asu + st * (HST * 2);
        const uint32_t sb = bsu + st * (HST * 2);
#pragma unroll
        for (int i = 0; i < 2; i++) {
            const int idx = tid + i * 128;     // 0..255
            const int row = idx >> 1;
            const int hf  = (idx & 1) * 8;     // half-offset within k16
            cp16(sa + (row * PADH + hf) * 2, A  + (long)(bm + row) * 1024 + k0 + hf);
            cp16(sb + (row * PADH + hf) * 2, Bt + (long)(bn + row) * 1024 + k0 + hf);
        }
        CP_COMMIT();
    };

    load_stage(0, 0);
    load_stage(1, 1);
    load_stage(2, 2);

    const int fr = lane >> 2;
    const int kp = (lane & 3) * 2;

    for (int kt = 0; kt < 64; kt++) {
        const int st = kt - (kt / 3) * 3;
        if (kt <= 61)      asm volatile("cp.async.wait_group 2;" ::: "memory");
        else if (kt == 62) asm volatile("cp.async.wait_group 1;" ::: "memory");
        else               asm volatile("cp.async.wait_group 0;" ::: "memory");
        __syncthreads();

        const __half* as = smh + st * HST;
        const __half* bs = smh + 3 * HST + st * HST;

        unsigned af[4][4], bf[8][2];
#pragma unroll
        for (int mt = 0; mt < 4; mt++) {
            const int r0 = warpM + mt * 16 + fr;
            af[mt][0] = *(const unsigned*)(as + r0 * PADH + kp);
            af[mt][1] = *(const unsigned*)(as + (r0 + 8) * PADH + kp);
            af[mt][2] = *(const unsigned*)(as + r0 * PADH + kp + 8);
            af[mt][3] = *(const unsigned*)(as + (r0 + 8) * PADH + kp + 8);
        }
#pragma unroll
        for (int nt = 0; nt < 8; nt++) {
            const int n = warpN + nt * 8 + fr;
            bf[nt][0] = *(const unsigned*)(bs + n * PADH + kp);
            bf[nt][1] = *(const unsigned*)(bs + n * PADH + kp + 8);
        }
#pragma unroll
        for (int mt = 0; mt < 4; mt++)
#pragma unroll
            for (int nt = 0; nt < 8; nt++)
                mma_f16(acc[mt][nt], af[mt][0], af[mt][1], af[mt][2], af[mt][3],
                        bf[nt][0], bf[nt][1]);

        __syncthreads();
        if (kt + 3 < 64) load_stage(kt + 3, st);
    }

#pragma unroll
    for (int mt = 0; mt < 4; mt++) {
        const int r0 = bm + warpM + mt * 16 + (lane >> 2);
#pragma unroll
        for (int nt = 0; nt < 8; nt++) {
            const int c = bn + warpN + nt * 8 + ((lane & 3) << 1);
            float v0 = acc[mt][nt][0], v1 = acc[mt][nt][1];
            float v2 = acc[mt][nt][2], v3 = acc[mt][nt][3];
            if (do_silu) {
                v0 = v0 / (1.f + expf(-v0));
                v1 = v1 / (1.f + expf(-v1));
                v2 = v2 / (1.f + expf(-v2));
                v3 = v3 / (1.f + expf(-v3));
            }
            *(float2*)(C + (long)r0 * N + c)       = make_float2(v0, v1);
            *(float2*)(C + (long)(r0 + 8) * N + c) = make_float2(v2, v3);
        }
    }
}

__global__ __launch_bounds__(128) void proj_gemm_kernel()
{
    const int z = blockIdx.z;
    const __half* W = g_Wh + (long)z * (Dd * INNER);
    float* O;
    bool silu = false;
    switch (z) {
        case 0:  O = g_Xq; break;
        case 1:  O = g_Xk; break;
        case 2:  O = g_Xv; break;
        default: O = g_Xg; silu = true; break;
    }
    hgemm128(g_xh, W, O, INNER, blockIdx.y * 128, blockIdx.x * 128, silu);
}

__global__ __launch_bounds__(128) void out_gemm_kernel(float* __restrict__ out)
{
    hgemm128(g_Yh, g_Wh + 4L * Dd * INNER, out, Dd,
             blockIdx.y * 128, blockIdx.x * 128, false);
}

// ---------------- pre-passes -------------------------------------------------
// x -> fp16 (8 elems/thread)
__global__ __launch_bounds__(256) void cvt_kernel(const float* __restrict__ x)
{
    const long i = ((long)blockIdx.x * 256 + threadIdx.x) * 8;
    float4 v0 = *(const float4*)(x + i);
    float4 v1 = *(const float4*)(x + i + 4);
    __half2 h[4];
    h[0] = __floats2half2_rn(v0.x, v0.y);
    h[1] = __floats2half2_rn(v0.z, v0.w);
    h[2] = __floats2half2_rn(v1.x, v1.y);
    h[3] = __floats2half2_rn(v1.z, v1.w);
    *(uint4*)(g_xh + i) = *(const uint4*)h;
}

// transpose + fp16: W (k-major 1024x1024) -> g_Wh slice (n-major)
__global__ __launch_bounds__(256) void wtrans_kernel(
    const float* __restrict__ Wq, const float* __restrict__ Wk,
    const float* __restrict__ Wv, const float* __restrict__ Wg,
    const float* __restrict__ Wo)
{
    const float* W;
    switch (blockIdx.z) {
        case 0: W = Wq; break;
        case 1: W = Wk; break;
        case 2: W = Wv; break;
        case 3: W = Wg; break;
        default: W = Wo; break;
    }
    __half* Out = g_Wh + (long)blockIdx.z * (Dd * INNER);
    __shared__ float t[32][33];
    const int tx = threadIdx.x & 31;
    const int ty = threadIdx.x >> 5;
    const int bx = blockIdx.x * 32;    // n block
    const int by = blockIdx.y * 32;    // k block
#pragma unroll
    for (int i = 0; i < 4; i++)
        t[ty + i * 8][tx] = W[(long)(by + ty + i * 8) * 1024 + bx + tx];
    __syncthreads();
#pragma unroll
    for (int i = 0; i < 4; i++)
        Out[(long)(bx + ty + i * 8) * 1024 + by + tx] = __float2half_rn(t[tx][ty + i * 8]);
}

// ---------------- conv (z<3) + alpha/beta mini-GEMM (z==3) -------------------
__global__ __launch_bounds__(128) void convab_kernel(
    const float* __restrict__ x,
    const float* __restrict__ cq_w, const float* __restrict__ cq_b,
    const float* __restrict__ ck_w, const float* __restrict__ ck_b,
    const float* __restrict__ cv_w, const float* __restrict__ cv_b,
    const float* __restrict__ Wa, const float* __restrict__ ba,
    const float* __restrict__ Wb, const float* __restrict__ bb)
{
    __shared__ float s_ab[32 * 65 + 64 * 33];

    if (blockIdx.z == 3) {
        if (blockIdx.x >= 128 || blockIdx.y != 0) return;
        const int blk = blockIdx.x;
        const int tid = threadIdx.x;
        float* xs = s_ab;
        float* ws = s_ab + 32 * 65;
        const int mrow = tid >> 2;
        const int ogrp = tid & 3;

        float acc[8];
#pragma unroll
        for (int j = 0; j < 8; j++) acc[j] = 0.f;

        for (int k0 = 0; k0 < Dd; k0 += 64) {
#pragma unroll
            for (int i = 0; i < 4; i++) {
                const int idx = tid + i * 128;
                const int row = idx >> 4;
                const int c4  = (idx & 15) << 2;
                float4 v = *(const float4*)(x + (long)(blk * 32 + row) * Dd + k0 + c4);
                xs[row * 65 + c4 + 0] = v.x;
                xs[row * 65 + c4 + 1] = v.y;
                xs[row * 65 + c4 + 2] = v.z;
                xs[row * 65 + c4 + 3] = v.w;
            }
#pragma unroll
            for (int i = 0; i < 16; i++) {
                const int idx = tid + i * 128;
                const int row = idx >> 5;
                const int col = idx & 31;
                ws[row * 33 + col] = (col < 16) ? Wa[(k0 + row) * Hh + col]
                                                : Wb[(k0 + row) * Hh + col - 16];
            }
            __syncthreads();
#pragma unroll 8
            for (int k = 0; k < 64; k++) {
                const float xv = xs[mrow * 65 + k];
#pragma unroll
                for (int j = 0; j < 8; j++)
                    acc[j] = fmaf(xv, ws[k * 33 + ogrp * 8 + j], acc[j]);
            }
            __syncthreads();
        }
#pragma unroll
        for (int j = 0; j < 8; j++) {
            const int o = ogrp * 8 + j;
            const float bias = (o < 16) ? ba[o] : bb[o - 16];
            g_AB[(long)(blk * 32 + mrow) * 32 + o] =
                1.f / (1.f + expf(-(acc[j] + bias)));
        }
        return;
    }

    const float* Xin; float* Out; const float* cw; const float* cb; bool donorm;
    switch (blockIdx.z) {
        case 0:  Xin = g_Xq; Out = g_Qn; cw = cq_w; cb = cq_b; donorm = true;  break;
        case 1:  Xin = g_Xk; Out = g_Kn; cw = ck_w; cb = ck_b; donorm = true;  break;
        default: Xin = g_Xv; Out = g_Vv; cw = cv_w; cb = cv_b; donorm = false; break;
    }
    const int bt0 = blockIdx.x * 16;
    const int t0  = bt0 & (Tt - 1);
    const int lane = threadIdx.x & 31;
    const int wid  = threadIdx.x >> 5;
    const int h = blockIdx.y * 4 + wid;
    const int c0 = h * 64 + lane;

    float x0[19], x1[19];
#pragma unroll
    for (int i = 0; i < 19; i++) {
        const int t = t0 - 3 + i;
        if (t < 0) { x0[i] = 0.f; x1[i] = 0.f; }
        else {
            const long g = (long)(bt0 - t0 + t) * INNER + c0;
            x0[i] = Xin[g];
            x1[i] = Xin[g + 32];
        }
    }
    float w0[4], w1[4];
#pragma unroll
    for (int k = 0; k < 4; k++) {
        w0[k] = cw[c0 * 4 + k];
        w1[k] = cw[(c0 + 32) * 4 + k];
    }
    const float b0 = cb[c0], b1 = cb[c0 + 32];

#pragma unroll
    for (int tt = 0; tt < 16; tt++) {
        float a0 = b0, a1 = b1;
#pragma unroll
        for (int k = 0; k < 4; k++) {
            a0 = fmaf(x0[tt + k], w0[k], a0);
            a1 = fmaf(x1[tt + k], w1[k], a1);
        }
        float s0 = a0 / (1.f + expf(-a0));
        float s1 = a1 / (1.f + expf(-a1));
        float ss = s0 * s0 + s1 * s1;
        ss += __shfl_xor_sync(0xffffffffu, ss, 16);
        ss += __shfl_xor_sync(0xffffffffu, ss, 8);
        ss += __shfl_xor_sync(0xffffffffu, ss, 4);
        ss += __shfl_xor_sync(0xffffffffu, ss, 2);
        ss += __shfl_xor_sync(0xffffffffu, ss, 1);
        if (donorm) {
            const float inv = 1.f / fmaxf(sqrtf(ss), 1e-12f);
            s0 *= inv; s1 *= inv;
        }
        const long g = (long)(bt0 + tt) * INNER + c0;
        Out[g] = s0;
        Out[g + 32] = s1;
    }
}

// ============== chunked delta-rule scan ======================================

__global__ __launch_bounds__(256, 2) void chunk_prep_kernel()
{
    extern __shared__ float sm[];
    float* sK = sm;
    float* sV = sm + 64 * CP;
    float* sL = sm + 2 * 64 * CP;
    float* sGam = sm + 3 * 64 * CP;
    float* sR   = sGam + 64;

    const int chunk = blockIdx.x;
    const int c  = chunk & (NCHUNK - 1);
    const int bh = chunk >> 5;
    const int b = bh >> 4, h = bh & 15;
    const int tid = threadIdx.x;
    const long rowbase = (long)b * Tt + c * 64;
    const int colbase = h * dh;
    const long cb = (long)chunk * 4096;

    for (int idx = tid; idx < 1024; idx += 256) {
        const int row = idx >> 4;
        const int c4  = (idx & 15) << 2;
        const long g = (rowbase + row) * INNER + colbase + c4;
        float4 kv = *(const float4*)(g_Kn + g);
        float4 vv = *(const float4*)(g_Vv + g);
        sK[row * CP + c4 + 0] = kv.x; sK[row * CP + c4 + 1] = kv.y;
        sK[row * CP + c4 + 2] = kv.z; sK[row * CP + c4 + 3] = kv.w;
        sV[row * CP + c4 + 0] = vv.x; sV[row * CP + c4 + 1] = vv.y;
        sV[row * CP + c4 + 2] = vv.z; sV[row * CP + c4 + 3] = vv.w;
    }
    if (tid < 64) {
        sGam[tid] = g_AB[(rowbase + tid) * 32 + h];
        sR[tid]   = g_AB[(rowbase + tid) * 32 + 16 + h];
    }
    __syncthreads();
    if (tid == 0) {
        float p = 1.f;
        for (int i = 0; i < 64; i++) { p *= sGam[i]; sGam[i] = p; }
    }
    __syncthreads();
    if (tid < 64) sR[tid] = sR[tid] / sGam[tid];
    __syncthreads();

    const int ty = tid >> 4, tx = tid & 15;

    {
        float acc[4][4];
#pragma unroll
        for (int v = 0; v < 4; v++)
#pragma unroll
            for (int u = 0; u < 4; u++) acc[v][u] = 0.f;
        for (int k = 0; k < 64; k++) {
            float a[4], bb[4];
#pragma unroll
            for (int v = 0; v < 4; v++) a[v]  = sK[(ty + 16 * v) * CP + k];
#pragma unroll
            for (int u = 0; u < 4; u++) bb[u] = sK[(tx + 16 * u) * CP + k];
#pragma unroll
            for (int v = 0; v < 4; v++)
#pragma unroll
                for (int u = 0; u < 4; u++)
                    acc[v][u] = fmaf(a[v], bb[u], acc[v][u]);
        }
#pragma unroll
        for (int v = 0; v < 4; v++)
#pragma unroll
            for (int u = 0; u < 4; u++) {
                const int j = ty + 16 * v, i = tx + 16 * u;
                sL[j * CP + i] = (i < j) ? acc[v][u] * sGam[j] * sR[i] : 0.f;
            }
        __syncthreads();
    }

    float rr_[64];
    const int col = tid & 63;
    const int isW = (tid >> 6) & 1;
    if (tid < 128) {
#pragma unroll
        for (int j = 0; j < 64; j++)
            rr_[j] = isW ? sGam[j] * sK[j * CP + col] : sV[j * CP + col];
#pragma unroll
        for (int j = 0; j < 64; j++) {
            const float xj = rr_[j];
#pragma unroll
            for (int i = j + 1; i < 64; i++)
                rr_[i] -= sL[i * CP + j] * xj;
        }
    }
    __syncthreads();

    const float gC = sGam[63];
    if (tid < 128) {
        float* dst  = isW ? sL : sV;
        float* gdst = isW ? g_W : g_T;
#pragma unroll
        for (int j = 0; j < 64; j++) {
            dst[j * CP + col] = rr_[j];
            gdst[cb + j * 64 + col] = rr_[j];
        }
    } else {
        const int t2 = tid - 128;
        for (int idx = t2; idx < 4096; idx += 128) {
            const int j = idx >> 6;
            sK[j * CP + (idx & 63)] *= gC * sR[j];
        }
    }
    if (tid < 64) {
        g_gam[chunk * 64 + tid] = sGam[tid];
        g_r  [chunk * 64 + tid] = sR[tid];
    }
    __syncthreads();

    {
        float am[4][4], an[4][4];
#pragma unroll
        for (int v = 0; v < 4; v++)
#pragma unroll
            for (int u = 0; u < 4; u++) {
                am[v][u] = ((ty == tx) && (v == u)) ? gC : 0.f;
                an[v][u] = 0.f;
            }
        for (int j = 0; j < 64; j++) {
            float wv[4], tv[4], kb[4];
#pragma unroll
            for (int v = 0; v < 4; v++) {
                wv[v] = sL[j * CP + ty + 16 * v];
                tv[v] = sV[j * CP + ty + 16 * v];
            }
#pragma unroll
            for (int u = 0; u < 4; u++) kb[u] = sK[j * CP + tx + 16 * u];
#pragma unroll
            for (int v = 0; v < 4; v++)
#pragma unroll
                for (int u = 0; u < 4; u++) {
                    am[v][u] = fmaf(-wv[v], kb[u], am[v][u]);
                    an[v][u] = fmaf( tv[v], kb[u], an[v][u]);
                }
        }
#pragma unroll
        for (int v = 0; v < 4; v++)
#pragma unroll
            for (int u = 0; u < 4; u++) {
                const int p = ty + 16 * v, q = tx + 16 * u;
                g_M[cb + p * 64 + q] = am[v][u];
                g_N[cb + p * 64 + q] = an[v][u];
            }
    }
}

__global__ __launch_bounds__(256) void chunk_scan_kernel()
{
    __shared__ float sS[16 * 64];
    __shared__ float sM[64 * 64];
    const int bh = blockIdx.x;
    const int R0 = blockIdx.y * 16;
    const int tid = threadIdx.x;
    const int row = tid >> 4;
    const int tx  = tid & 15;

    for (int idx = tid; idx < 1024; idx += 256) sS[idx] = 0.f;
    __syncthreads();

    for (int c = 0; c < NCHUNK; c++) {
        const long cb = (long)(bh * NCHUNK + c) * 4096;
        for (int idx = tid; idx < 1024; idx += 256)
            g_S0[cb + (long)(R0 + (idx >> 6)) * 64 + (idx & 63)] = sS[idx];
        for (int idx = tid; idx < 4096; idx += 256)
            sM[idx] = g_M[cb + idx];
        __syncthreads();

        float acc[4];
#pragma unroll
        for (int u = 0; u < 4; u++)
            acc[u] = g_N[cb + (long)(R0 + row) * 64 + tx + 16 * u];
        for (int k = 0; k < 64; k++) {
            const float s = sS[row * 64 + k];
#pragma unroll
            for (int u = 0; u < 4; u++)
                acc[u] = fmaf(s, sM[k * 64 + tx + 16 * u], acc[u]);
        }
        __syncthreads();
#pragma unroll
        for (int u = 0; u < 4; u++) sS[row * 64 + tx + 16 * u] = acc[u];
        __syncthreads();
    }
}

// ---- chunk_out: tensor-core (tf32 mma) version ------------------------------
#define CO_SMEM ((6 * 64 * CO + 128) * 4)

__device__ __forceinline__ void mma_block64(const float* __restrict__ As_,
                                            const float* __restrict__ Bs_,
                                            int m0, int n0, int lane,
                                            float acc[2][2][4])
{
#pragma unroll
    for (int k8 = 0; k8 < 64; k8 += 8) {
        const int kk0 = k8 + (lane & 3);
        const int kk1 = kk0 + 4;
        unsigned af[2][4], bf[2][2];
#pragma unroll
        for (int mt = 0; mt < 2; mt++) {
            const int r0 = m0 + mt * 16 + (lane >> 2);
            af[mt][0] = __float_as_uint(As_[r0 * CO + kk0]);
            af[mt][1] = __float_as_uint(As_[(r0 + 8) * CO + kk0]);
            af[mt][2] = __float_as_uint(As_[r0 * CO + kk1]);
            af[mt][3] = __float_as_uint(As_[(r0 + 8) * CO + kk1]);
        }
#pragma unroll
        for (int nt = 0; nt < 2; nt++) {
            const int n = n0 + nt * 8 + (lane >> 2);
            bf[nt][0] = __float_as_uint(Bs_[n * CO + kk0]);
            bf[nt][1] = __float_as_uint(Bs_[n * CO + kk1]);
        }
#pragma unroll
        for (int mt = 0; mt < 2; mt++)
#pragma unroll
            for (int nt = 0; nt < 2; nt++)
                mma_tf32(acc[mt][nt], af[mt][0], af[mt][1], af[mt][2], af[mt][3],
                         bf[nt][0], bf[nt][1]);
    }
}

__global__ __launch_bounds__(256, 2) void chunk_out_kernel()
{
    extern __shared__ float sm[];
    float* sQg = sm;
    float* sK  = sm + 64 * CO;
    float* sS0 = sm + 2 * 64 * CO;
    float* sW  = sm + 3 * 64 * CO;
    float* sT  = sm + 4 * 64 * CO;
    float* sA  = sm + 5 * 64 * CO;
    float* sGam = sm + 6 * 64 * CO;
    float* sR   = sGam + 64;
    float* sUT  = sK;

    const int chunk = blockIdx.x;
    const int c  = chunk & (NCHUNK - 1);
    const int bh = chunk >> 5;
    const int b = bh >> 4, h = bh & 15;
    const int tid = threadIdx.x;
    const int lane = tid & 31;
    const int wid  = tid >> 5;
    const int m0 = (wid & 1) * 32;
    const int n0 = (wid >> 1) * 16;
    const long rowbase = (long)b * Tt + c * 64;
    const int colbase = h * dh;
    const long cb = (long)chunk * 4096;

    if (tid < 64) {
        sGam[tid] = g_gam[chunk * 64 + tid];
        sR[tid]   = g_r[chunk * 64 + tid];
    }
    __syncthreads();

    for (int idx = tid; idx < 1024; idx += 256) {
        const int row = idx >> 4;
        const int c4  = (idx & 15) << 2;
        const long g = (rowbase + row) * INNER + colbase + c4;
        float4 qv = *(const float4*)(g_Qn + g);
        float4 kv = *(const float4*)(g_Kn + g);
        const float gm = sGam[row];
        sQg[row * CO + c4 + 0] = rna_tf32(qv.x * gm);
        sQg[row * CO + c4 + 1] = rna_tf32(qv.y * gm);
        sQg[row * CO + c4 + 2] = rna_tf32(qv.z * gm);
        sQg[row * CO + c4 + 3] = rna_tf32(qv.w * gm);
        sK [row * CO + c4 + 0] = rna_tf32(kv.x);
        sK [row * CO + c4 + 1] = rna_tf32(kv.y);
        sK [row * CO + c4 + 2] = rna_tf32(kv.z);
        sK [row * CO + c4 + 3] = rna_tf32(kv.w);
    }
    for (int idx = tid; idx < 4096; idx += 256) {
        const int r = idx >> 6, cc = idx & 63;
        sS0[r * CO + cc] = rna_tf32(g_S0[cb + idx]);
        sW [r * CO + cc] = rna_tf32(g_W[cb + idx]);
        sT [r * CO + cc] = g_T[cb + idx];
    }
    __syncthreads();

    // Phase 1: A = tril(diag(gam) Q K^T diag(r))
    {
        float acc[2][2][4];
#pragma unroll
        for (int mt = 0; mt < 2; mt++)
#pragma unroll
            for (int nt = 0; nt < 2; nt++)
#pragma unroll
                for (int i = 0; i < 4; i++) acc[mt][nt][i] = 0.f;
        mma_block64(sQg, sK, m0, n0, lane, acc);
        __syncthreads();
#pragma unroll
        for (int mt = 0; mt < 2; mt++) {
            const int t0r = m0 + mt * 16 + (lane >> 2);
#pragma unroll
            for (int nt = 0; nt < 2; nt++) {
                const int j0 = n0 + nt * 8 + ((lane & 3) << 1);
#pragma unroll
                for (int half = 0; half < 2; half++) {
                    const int t = t0r + half * 8;
                    const float v0 = acc[mt][nt][half * 2 + 0];
                    const float v1 = acc[mt][nt][half * 2 + 1];
                    sA[t * CO + j0]     = (j0     <= t) ? rna_tf32(v0 * sR[j0])     : 0.f;
                    sA[t * CO + j0 + 1] = (j0 + 1 <= t) ? rna_tf32(v1 * sR[j0 + 1]) : 0.f;
                }
            }
        }
    }

    // Phase 2: UT[a][j] = T[j][a] - (S0 W^T)(a,j)
    {
        float acc[2][2][4];
#pragma unroll
        for (int mt = 0; mt < 2; mt++)
#pragma unroll
            for (int nt = 0; nt < 2; nt++)
#pragma unroll
                for (int i = 0; i < 4; i++) acc[mt][nt][i] = 0.f;
        mma_block64(sS0, sW, m0, n0, lane, acc);
        __syncthreads();
#pragma unroll
        for (int mt = 0; mt < 2; mt++) {
            const int a0 = m0 + mt * 16 + (lane >> 2);
#pragma unroll
            for (int nt = 0; nt < 2; nt++) {
                const int j0 = n0 + nt * 8 + ((lane & 3) << 1);
#pragma unroll
                for (int half = 0; half < 2; half++) {
                    const int a = a0 + half * 8;
                    sUT[a * CO + j0]     = rna_tf32(sT[j0 * CO + a]       - acc[mt][nt][half * 2 + 0]);
                    sUT[a * CO + j0 + 1] = rna_tf32(sT[(j0 + 1) * CO + a] - acc[mt][nt][half * 2 + 1]);
                }
            }
        }
    }
    __syncthreads();

    // Phase 3: O = Qg S0^T + A U
    {
        float acc[2][2][4];
#pragma unroll
        for (int mt = 0; mt < 2; mt++)
#pragma unroll
            for (int nt = 0; nt < 2; nt++)
#pragma unroll
                for (int i = 0; i < 4; i++) acc[mt][nt][i] = 0.f;
        mma_block64(sQg, sS0, m0, n0, lane, acc);
        mma_block64(sA, sUT, m0, n0, lane, acc);
#pragma unroll
        for (int mt = 0; mt < 2; mt++) {
            const int t0r = m0 + mt * 16 + (lane >> 2);
#pragma unroll
            for (int nt = 0; nt < 2; nt++) {
                const int a0 = n0 + nt * 8 + ((lane & 3) << 1);
#pragma unroll
                for (int half = 0; half < 2; half++) {
                    const int t = t0r + half * 8;
                    *(float2*)(g_O + (rowbase + t) * INNER + colbase + a0) =
                        make_float2(acc[mt][nt][half * 2 + 0],
                                    acc[mt][nt][half * 2 + 1]);
                }
            }
        }
    }
}

// ---------------- RMS norm + (1+gamma) + gate -> fp16 ------------------------
__global__ __launch_bounds__(256) void rmsgate_kernel(const float* __restrict__ gamma)
{
    const int m = blockIdx.x;
    const int tid = threadIdx.x;
    const long base = (long)m * INNER + tid * 4;
    float4 xv = *(const float4*)(g_O + base);
    float ss = xv.x * xv.x + xv.y * xv.y + xv.z * xv.z + xv.w * xv.w;
    for (int off = 16; off; off >>= 1) ss += __shfl_xor_sync(0xffffffffu, ss, off);
    __shared__ float red[8];
    if ((tid & 31) == 0) red[tid >> 5] = ss;
    __syncthreads();
    float tot = 0.f;
#pragma unroll
    for (int w = 0; w < 8; w++) tot += red[w];
    const float inv = 1.f / sqrtf(tot * (1.f / (float)INNER) + 1e-6f);
    float4 gv = *(const float4*)(g_Xg + base);
    float4 gm = *(const float4*)(gamma + tid * 4);
    __half2 h[2];
    h[0] = __floats2half2_rn(xv.x * inv * (1.f + gm.x) * gv.x,
                             xv.y * inv * (1.f + gm.y) * gv.y);
    h[1] = __floats2half2_rn(xv.z * inv * (1.f + gm.z) * gv.z,
                             xv.w * inv * (1.f + gm.w) * gv.w);
    *(uint2*)(g_Yh + base) = *(const uint2*)h;
}

// ---------------- launch -----------------------------------------------------
extern "C" void kernel_launch(void* const* d_in, const int* in_sizes, int n_in,
                              void* d_out, int out_size)
{
    const float* x    = (const float*)d_in[0];
    const float* Wq   = (const float*)d_in[1];
    const float* Wk   = (const float*)d_in[2];
    const float* Wv   = (const float*)d_in[3];
    const float* Wa   = (const float*)d_in[4];
    const float* ba   = (const float*)d_in[5];
    const float* Wb   = (const float*)d_in[6];
    const float* bb   = (const float*)d_in[7];
    const float* Wg   = (const float*)d_in[8];
    const float* Wo   = (const float*)d_in[9];
    const float* cq_w = (const float*)d_in[10];
    const float* cq_b = (const float*)d_in[11];
    const float* ck_w = (const float*)d_in[12];
    const float* ck_b = (const float*)d_in[13];
    const float* cv_w = (const float*)d_in[14];
    const float* cv_b = (const float*)d_in[15];
    const float* gamma= (const float*)d_in[16];
    float* out = (float*)d_out;

    const int prep_smem = (3 * 64 * CP + 128) * sizeof(float);
    cudaFuncSetAttribute(chunk_prep_kernel,
                         cudaFuncAttributeMaxDynamicSharedMemorySize, prep_smem);
    cudaFuncSetAttribute(chunk_out_kernel,
                         cudaFuncAttributeMaxDynamicSharedMemorySize, CO_SMEM);
    cudaFuncSetAttribute(proj_gemm_kernel,
                         cudaFuncAttributeMaxDynamicSharedMemorySize, GSMEM);
    cudaFuncSetAttribute(out_gemm_kernel,
                         cudaFuncAttributeMaxDynamicSharedMemorySize, GSMEM);

    cvt_kernel<<<Mrows * Dd / 2048, 256>>>(x);
    wtrans_kernel<<<dim3(32, 32, 5), 256>>>(Wq, Wk, Wv, Wg, Wo);
    proj_gemm_kernel<<<dim3(INNER / 128, Mrows / 128, 4), 128, GSMEM>>>();
    convab_kernel<<<dim3(Mrows / 16, 4, 4), 128>>>(x, cq_w, cq_b, ck_w, ck_b,
                                                   cv_w, cv_b, Wa, ba, Wb, bb);
    chunk_prep_kernel<<<1024, 256, prep_smem>>>();
    chunk_scan_kernel<<<dim3(Bz * Hh, 4), 256>>>();
    chunk_out_kernel<<<1024, 256, CO_SMEM>>>();
    rmsgate_kernel<<<Mrows, 256>>>(gamma);
    out_gemm_kernel<<<dim3(Dd / 128, Mrows / 128), 128, GSMEM>>>(out);
}

// round 12
// speedup vs baseline: 1.2013x; 1.0278x over previous
#include <cuda_runtime.h>
#include <cuda_fp16.h>
#include <math.h>
#include <stdint.h>

// Problem constants
#define Bz 2
#define Tt 2048
#define Dd 1024
#define Hh 16
#define dh 64
#define INNER 1024
#define Mrows 4096   // B*T
#define NCHUNK 32
#define CP 65        // padded stride for 64x64 smem tiles (SIMT kernels)
#define CO 68        // padded stride for mma tiles

// ---------------- scratch ----------------------------------------------------
__device__ float g_Xq[Mrows * INNER];
__device__ float g_Xk[Mrows * INNER];
__device__ float g_Xv[Mrows * INNER];
__device__ float g_Xg[Mrows * INNER];
__device__ float g_Qn[Mrows * INNER];
__device__ float g_Kn[Mrows * INNER];
__device__ float g_Vv[Mrows * INNER];
__device__ float g_AB[Mrows * 32];
__device__ float g_O [Mrows * INNER];
__device__ __half g_xh[Mrows * Dd];        // fp16 x
__device__ __half g_Wh[5 * Dd * INNER];    // fp16 TRANSPOSED weights [n][k]
__device__ __half g_Yh[Mrows * INNER];     // fp16 rms*gamma*gate
__device__ float g_T [1024 * 4096];
__device__ float g_W [1024 * 4096];
__device__ float g_M [1024 * 4096];
__device__ float g_N [1024 * 4096];
__device__ float g_S0[1024 * 4096];
__device__ float g_gam[1024 * 64];
__device__ float g_r  [1024 * 64];

// ---------------- helpers ----------------------------------------------------
__device__ __forceinline__ unsigned cvt_tf32(float f) {
    unsigned u;
    asm("cvt.rna.tf32.f32 %0, %1;" : "=r"(u) : "f"(f));
    return u;
}
__device__ __forceinline__ float rna_tf32(float f) {
    return __uint_as_float(cvt_tf32(f));
}
__device__ __forceinline__ uint32_t smem_u32(const void* p) {
    uint32_t a;
    asm("{ .reg .u64 t; cvta.to.shared.u64 t, %1; cvt.u32.u64 %0, t; }"
        : "=r"(a) : "l"(p));
    return a;
}
__device__ __forceinline__ void cp16(uint32_t saddr, const void* gptr) {
    asm volatile("cp.async.cg.shared.global [%0], [%1], 16;" :: "r"(saddr), "l"(gptr));
}
#define CP_COMMIT() asm volatile("cp.async.commit_group;" ::: "memory")

__device__ __forceinline__ void mma_tf32(float* d, unsigned a0, unsigned a1,
                                         unsigned a2, unsigned a3,
                                         unsigned b0, unsigned b1) {
    asm("mma.sync.aligned.m16n8k8.row.col.f32.tf32.tf32.f32 "
        "{%0,%1,%2,%3}, {%4,%5,%6,%7}, {%8,%9}, {%0,%1,%2,%3};\n"
        : "+f"(d[0]), "+f"(d[1]), "+f"(d[2]), "+f"(d[3])
        : "r"(a0), "r"(a1), "r"(a2), "r"(a3), "r"(b0), "r"(b1));
}

__device__ __forceinline__ void mma_f16(float* d, unsigned a0, unsigned a1,
                                        unsigned a2, unsigned a3,
                                        unsigned b0, unsigned b1) {
    asm("mma.sync.aligned.m16n8k16.row.col.f32.f16.f16.f32 "
        "{%0,%1,%2,%3}, {%4,%5,%6,%7}, {%8,%9}, {%0,%1,%2,%3};\n"
        : "+f"(d[0]), "+f"(d[1]), "+f"(d[2]), "+f"(d[3])
        : "r"(a0), "r"(a1), "r"(a2), "r"(a3), "r"(b0), "r"(b1));
}

// 64x64x64 tf32 mma block: acc[m][n] += sum_k As_[m][k]*Bs_[n][k], CO stride.
__device__ __forceinline__ void mma_block64(const float* __restrict__ As_,
                                            const float* __restrict__ Bs_,
                                            int m0, int n0, int lane,
                                            float acc[2][2][4])
{
#pragma unroll
    for (int k8 = 0; k8 < 64; k8 += 8) {
        const int kk0 = k8 + (lane & 3);
        const int kk1 = kk0 + 4;
        unsigned af[2][4], bf[2][2];
#pragma unroll
        for (int mt = 0; mt < 2; mt++) {
            const int r0 = m0 + mt * 16 + (lane >> 2);
            af[mt][0] = __float_as_uint(As_[r0 * CO + kk0]);
            af[mt][1] = __float_as_uint(As_[(r0 + 8) * CO + kk0]);
            af[mt][2] = __float_as_uint(As_[r0 * CO + kk1]);
            af[mt][3] = __float_as_uint(As_[(r0 + 8) * CO + kk1]);
        }
#pragma unroll
        for (int nt = 0; nt < 2; nt++) {
            const int n = n0 + nt * 8 + (lane >> 2);
            bf[nt][0] = __float_as_uint(Bs_[n * CO + kk0]);
            bf[nt][1] = __float_as_uint(Bs_[n * CO + kk1]);
        }
#pragma unroll
        for (int mt = 0; mt < 2; mt++)
#pragma unroll
            for (int nt = 0; nt < 2; nt++)
                mma_tf32(acc[mt][nt], af[mt][0], af[mt][1], af[mt][2], af[mt][3],
                         bf[nt][0], bf[nt][1]);
    }
}

// ---------------- fp16 GEMM, 128x128 tile, cp.async 3-stage pipeline ---------
#define PADH 24
#define HST (128 * PADH)
#define GSMEM (6 * HST * 2)

__device__ __forceinline__ void hgemm128(const __half* __restrict__ A,
                                         const __half* __restrict__ Bt,
                                         float* __restrict__ C,
                                         int N, int bm, int bn,
                                         bool do_silu)
{
    extern __shared__ __half smh[];

    const int tid  = threadIdx.x;
    const int lane = tid & 31;
    const int wid  = tid >> 5;
    const int warpM = (wid & 1) * 64;
    const int warpN = (wid >> 1) * 64;

    float acc[4][8][4];
#pragma unroll
    for (int mt = 0; mt < 4; mt++)
#pragma unroll
        for (int nt = 0; nt < 8; nt++)
#pragma unroll
            for (int i = 0; i < 4; i++) acc[mt][nt][i] = 0.f;

    const uint32_t asu = smem_u32(smh);
    const uint32_t bsu = asu + 3 * HST * 2;

    auto load_stage = [&](int kt, int st) {
        const int k0 = kt << 4;
        const uint32_t sa = asu + st * (HST * 2);
        const uint32_t sb = bsu + st * (HST * 2);
#pragma unroll
        for (int i = 0; i < 2; i++) {
            const int idx = tid + i * 128;
            const int row = idx >> 1;
            const int hf  = (idx & 1) * 8;
            cp16(sa + (row * PADH + hf) * 2, A  + (long)(bm + row) * 1024 + k0 + hf);
            cp16(sb + (row * PADH + hf) * 2, Bt + (long)(bn + row) * 1024 + k0 + hf);
        }
        CP_COMMIT();
    };

    load_stage(0, 0);
    load_stage(1, 1);
    load_stage(2, 2);

    const int fr = lane >> 2;
    const int kp = (lane & 3) * 2;

    for (int kt = 0; kt < 64; kt++) {
        const int st = kt - (kt / 3) * 3;
        if (kt <= 61)      asm volatile("cp.async.wait_group 2;" ::: "memory");
        else if (kt == 62) asm volatile("cp.async.wait_group 1;" ::: "memory");
        else               asm volatile("cp.async.wait_group 0;" ::: "memory");
        __syncthreads();

        const __half* as = smh + st * HST;
        const __half* bs = smh + 3 * HST + st * HST;

        unsigned af[4][4], bf[8][2];
#pragma unroll
        for (int mt = 0; mt < 4; mt++) {
            const int r0 = warpM + mt * 16 + fr;
            af[mt][0] = *(const unsigned*)(as + r0 * PADH + kp);
            af[mt][1] = *(const unsigned*)(as + (r0 + 8) * PADH + kp);
            af[mt][2] = *(const unsigned*)(as + r0 * PADH + kp + 8);
            af[mt][3] = *(const unsigned*)(as + (r0 + 8) * PADH + kp + 8);
        }
#pragma unroll
        for (int nt = 0; nt < 8; nt++) {
            const int n = warpN + nt * 8 + fr;
            bf[nt][0] = *(const unsigned*)(bs + n * PADH + kp);
            bf[nt][1] = *(const unsigned*)(bs + n * PADH + kp + 8);
        }
#pragma unroll
        for (int mt = 0; mt < 4; mt++)
#pragma unroll
            for (int nt = 0; nt < 8; nt++)
                mma_f16(acc[mt][nt], af[mt][0], af[mt][1], af[mt][2], af[mt][3],
                        bf[nt][0], bf[nt][1]);

        __syncthreads();
        if (kt + 3 < 64) load_stage(kt + 3, st);
    }

#pragma unroll
    for (int mt = 0; mt < 4; mt++) {
        const int r0 = bm + warpM + mt * 16 + (lane >> 2);
#pragma unroll
        for (int nt = 0; nt < 8; nt++) {
            const int c = bn + warpN + nt * 8 + ((lane & 3) << 1);
            float v0 = acc[mt][nt][0], v1 = acc[mt][nt][1];
            float v2 = acc[mt][nt][2], v3 = acc[mt][nt][3];
            if (do_silu) {
                v0 = v0 / (1.f + expf(-v0));
                v1 = v1 / (1.f + expf(-v1));
                v2 = v2 / (1.f + expf(-v2));
                v3 = v3 / (1.f + expf(-v3));
            }
            *(float2*)(C + (long)r0 * N + c)       = make_float2(v0, v1);
            *(float2*)(C + (long)(r0 + 8) * N + c) = make_float2(v2, v3);
        }
    }
}

__global__ __launch_bounds__(128) void proj_gemm_kernel()
{
    const int z = blockIdx.z;
    const __half* W = g_Wh + (long)z * (Dd * INNER);
    float* O;
    bool silu = false;
    switch (z) {
        case 0:  O = g_Xq; break;
        case 1:  O = g_Xk; break;
        case 2:  O = g_Xv; break;
        default: O = g_Xg; silu = true; break;
    }
    hgemm128(g_xh, W, O, INNER, blockIdx.y * 128, blockIdx.x * 128, silu);
}

__global__ __launch_bounds__(128) void out_gemm_kernel(float* __restrict__ out)
{
    hgemm128(g_Yh, g_Wh + 4L * Dd * INNER, out, Dd,
             blockIdx.y * 128, blockIdx.x * 128, false);
}

// ---------------- pre-passes -------------------------------------------------
__global__ __launch_bounds__(256) void cvt_kernel(const float* __restrict__ x)
{
    const long i = ((long)blockIdx.x * 256 + threadIdx.x) * 8;
    float4 v0 = *(const float4*)(x + i);
    float4 v1 = *(const float4*)(x + i + 4);
    __half2 h[4];
    h[0] = __floats2half2_rn(v0.x, v0.y);
    h[1] = __floats2half2_rn(v0.z, v0.w);
    h[2] = __floats2half2_rn(v1.x, v1.y);
    h[3] = __floats2half2_rn(v1.z, v1.w);
    *(uint4*)(g_xh + i) = *(const uint4*)h;
}

__global__ __launch_bounds__(256) void wtrans_kernel(
    const float* __restrict__ Wq, const float* __restrict__ Wk,
    const float* __restrict__ Wv, const float* __restrict__ Wg,
    const float* __restrict__ Wo)
{
    const float* W;
    switch (blockIdx.z) {
        case 0: W = Wq; break;
        case 1: W = Wk; break;
        case 2: W = Wv; break;
        case 3: W = Wg; break;
        default: W = Wo; break;
    }
    __half* Out = g_Wh + (long)blockIdx.z * (Dd * INNER);
    __shared__ float t[32][33];
    const int tx = threadIdx.x & 31;
    const int ty = threadIdx.x >> 5;
    const int bx = blockIdx.x * 32;
    const int by = blockIdx.y * 32;
#pragma unroll
    for (int i = 0; i < 4; i++)
        t[ty + i * 8][tx] = W[(long)(by + ty + i * 8) * 1024 + bx + tx];
    __syncthreads();
#pragma unroll
    for (int i = 0; i < 4; i++)
        Out[(long)(bx + ty + i * 8) * 1024 + by + tx] = __float2half_rn(t[tx][ty + i * 8]);
}

// ---------------- conv (z<3, 8 t/thread) + alpha/beta GEMM (z==3) ------------
__global__ __launch_bounds__(128) void convab_kernel(
    const float* __restrict__ x,
    const float* __restrict__ cq_w, const float* __restrict__ cq_b,
    const float* __restrict__ ck_w, const float* __restrict__ ck_b,
    const float* __restrict__ cv_w, const float* __restrict__ cv_b,
    const float* __restrict__ Wa, const float* __restrict__ ba,
    const float* __restrict__ Wb, const float* __restrict__ bb)
{
    __shared__ float s_ab[32 * 65 + 64 * 33];

    if (blockIdx.z == 3) {
        if (blockIdx.x >= 128 || blockIdx.y != 0) return;
        const int blk = blockIdx.x;
        const int tid = threadIdx.x;
        float* xs = s_ab;
        float* ws = s_ab + 32 * 65;
        const int mrow = tid >> 2;
        const int ogrp = tid & 3;

        float acc[8];
#pragma unroll
        for (int j = 0; j < 8; j++) acc[j] = 0.f;

        for (int k0 = 0; k0 < Dd; k0 += 64) {
#pragma unroll
            for (int i = 0; i < 4; i++) {
                const int idx = tid + i * 128;
                const int row = idx >> 4;
                const int c4  = (idx & 15) << 2;
                float4 v = *(const float4*)(x + (long)(blk * 32 + row) * Dd + k0 + c4);
                xs[row * 65 + c4 + 0] = v.x;
                xs[row * 65 + c4 + 1] = v.y;
                xs[row * 65 + c4 + 2] = v.z;
                xs[row * 65 + c4 + 3] = v.w;
            }
#pragma unroll
            for (int i = 0; i < 16; i++) {
                const int idx = tid + i * 128;
                const int row = idx >> 5;
                const int col = idx & 31;
                ws[row * 33 + col] = (col < 16) ? Wa[(k0 + row) * Hh + col]
                                                : Wb[(k0 + row) * Hh + col - 16];
            }
            __syncthreads();
#pragma unroll 8
            for (int k = 0; k < 64; k++) {
                const float xv = xs[mrow * 65 + k];
#pragma unroll
                for (int j = 0; j < 8; j++)
                    acc[j] = fmaf(xv, ws[k * 33 + ogrp * 8 + j], acc[j]);
            }
            __syncthreads();
        }
#pragma unroll
        for (int j = 0; j < 8; j++) {
            const int o = ogrp * 8 + j;
            const float bias = (o < 16) ? ba[o] : bb[o - 16];
            g_AB[(long)(blk * 32 + mrow) * 32 + o] =
                1.f / (1.f + expf(-(acc[j] + bias)));
        }
        return;
    }

    const float* Xin; float* Out; const float* cw; const float* cb; bool donorm;
    switch (blockIdx.z) {
        case 0:  Xin = g_Xq; Out = g_Qn; cw = cq_w; cb = cq_b; donorm = true;  break;
        case 1:  Xin = g_Xk; Out = g_Kn; cw = ck_w; cb = ck_b; donorm = true;  break;
        default: Xin = g_Xv; Out = g_Vv; cw = cv_w; cb = cv_b; donorm = false; break;
    }
    const int bt0 = blockIdx.x * 8;
    const int t0  = bt0 & (Tt - 1);
    const int lane = threadIdx.x & 31;
    const int wid  = threadIdx.x >> 5;
    const int h = blockIdx.y * 4 + wid;
    const int c0 = h * 64 + lane;

    float x0[11], x1[11];
#pragma unroll
    for (int i = 0; i < 11; i++) {
        const int t = t0 - 3 + i;
        if (t < 0) { x0[i] = 0.f; x1[i] = 0.f; }
        else {
            const long g = (long)(bt0 - t0 + t) * INNER + c0;
            x0[i] = Xin[g];
            x1[i] = Xin[g + 32];
        }
    }
    float w0[4], w1[4];
#pragma unroll
    for (int k = 0; k < 4; k++) {
        w0[k] = cw[c0 * 4 + k];
        w1[k] = cw[(c0 + 32) * 4 + k];
    }
    const float b0 = cb[c0], b1 = cb[c0 + 32];

#pragma unroll
    for (int tt = 0; tt < 8; tt++) {
        float a0 = b0, a1 = b1;
#pragma unroll
        for (int k = 0; k < 4; k++) {
            a0 = fmaf(x0[tt + k], w0[k], a0);
            a1 = fmaf(x1[tt + k], w1[k], a1);
        }
        float s0 = a0 / (1.f + expf(-a0));
        float s1 = a1 / (1.f + expf(-a1));
        float ss = s0 * s0 + s1 * s1;
        ss += __shfl_xor_sync(0xffffffffu, ss, 16);
        ss += __shfl_xor_sync(0xffffffffu, ss, 8);
        ss += __shfl_xor_sync(0xffffffffu, ss, 4);
        ss += __shfl_xor_sync(0xffffffffu, ss, 2);
        ss += __shfl_xor_sync(0xffffffffu, ss, 1);
        if (donorm) {
            const float inv = 1.f / fmaxf(sqrtf(ss), 1e-12f);
            s0 *= inv; s1 *= inv;
        }
        const long g = (long)(bt0 + tt) * INNER + c0;
        Out[g] = s0;
        Out[g + 32] = s1;
    }
}

// ============== chunked delta-rule scan ======================================
// prep: L + solve in fp32; M,N via tf32 mma (error is decayed by gC ~ 3e-4).
#define PREP_SMEM ((3 * 64 * CP + 3 * 64 * CO + 128) * 4)

__global__ __launch_bounds__(256, 2) void chunk_prep_kernel()
{
    extern __shared__ float sm[];
    float* sK   = sm;                         // [64][CP] raw K
    float* sV   = sm + 64 * CP;               // [64][CP] raw V
    float* sL   = sm + 2 * 64 * CP;           // [64][CP] L
    float* sWT  = sm + 3 * 64 * CP;           // [64][CO] W^T (rounded)
    float* sTT  = sWT + 64 * CO;              // [64][CO] T^T (rounded)
    float* sKsT = sWT + 2 * 64 * CO;          // [64][CO] (gC r K)^T (rounded)
    float* sGam = sWT + 3 * 64 * CO;
    float* sR   = sGam + 64;

    const int chunk = blockIdx.x;
    const int c  = chunk & (NCHUNK - 1);
    const int bh = chunk >> 5;
    const int b = bh >> 4, h = bh & 15;
    const int tid = threadIdx.x;
    const long rowbase = (long)b * Tt + c * 64;
    const int colbase = h * dh;
    const long cb = (long)chunk * 4096;

    for (int idx = tid; idx < 1024; idx += 256) {
        const int row = idx >> 4;
        const int c4  = (idx & 15) << 2;
        const long g = (rowbase + row) * INNER + colbase + c4;
        float4 kv = *(const float4*)(g_Kn + g);
        float4 vv = *(const float4*)(g_Vv + g);
        sK[row * CP + c4 + 0] = kv.x; sK[row * CP + c4 + 1] = kv.y;
        sK[row * CP + c4 + 2] = kv.z; sK[row * CP + c4 + 3] = kv.w;
        sV[row * CP + c4 + 0] = vv.x; sV[row * CP + c4 + 1] = vv.y;
        sV[row * CP + c4 + 2] = vv.z; sV[row * CP + c4 + 3] = vv.w;
    }
    if (tid < 64) {
        sGam[tid] = g_AB[(rowbase + tid) * 32 + h];
        sR[tid]   = g_AB[(rowbase + tid) * 32 + 16 + h];
    }
    __syncthreads();
    if (tid == 0) {
        float p = 1.f;
        for (int i = 0; i < 64; i++) { p *= sGam[i]; sGam[i] = p; }
    }
    __syncthreads();
    if (tid < 64) sR[tid] = sR[tid] / sGam[tid];
    __syncthreads();

    const int ty = tid >> 4, tx = tid & 15;

    // L[j][i] = (i<j) ? gam[j]*r[i]*<k_i,k_j> : 0   (fp32 SIMT)
    {
        float acc[4][4];
#pragma unroll
        for (int v = 0; v < 4; v++)
#pragma unroll
            for (int u = 0; u < 4; u++) acc[v][u] = 0.f;
        for (int k = 0; k < 64; k++) {
            float a[4], bb[4];
#pragma unroll
            for (int v = 0; v < 4; v++) a[v]  = sK[(ty + 16 * v) * CP + k];
#pragma unroll
            for (int u = 0; u < 4; u++) bb[u] = sK[(tx + 16 * u) * CP + k];
#pragma unroll
            for (int v = 0; v < 4; v++)
#pragma unroll
                for (int u = 0; u < 4; u++)
                    acc[v][u] = fmaf(a[v], bb[u], acc[v][u]);
        }
#pragma unroll
        for (int v = 0; v < 4; v++)
#pragma unroll
            for (int u = 0; u < 4; u++) {
                const int j = ty + 16 * v, i = tx + 16 * u;
                sL[j * CP + i] = (i < j) ? acc[v][u] * sGam[j] * sR[i] : 0.f;
            }
        __syncthreads();
    }

    // solve (tid<128, fp32, in registers)  ||  build Ks^T (tid>=128)
    const float gC = sGam[63];
    float rr_[64];
    const int col = tid & 63;
    const int isW = (tid >> 6) & 1;
    if (tid < 128) {
#pragma unroll
        for (int j = 0; j < 64; j++)
            rr_[j] = isW ? sGam[j] * sK[j * CP + col] : sV[j * CP + col];
#pragma unroll
        for (int j = 0; j < 64; j++) {
            const float xj = rr_[j];
#pragma unroll
            for (int i = j + 1; i < 64; i++)
                rr_[i] -= sL[i * CP + j] * xj;
        }
    } else {
        const int t2 = tid - 128;
        for (int idx = t2; idx < 4096; idx += 128) {
            const int j = idx & 63, q = idx >> 6;
            sKsT[q * CO + j] = rna_tf32(gC * sR[j] * sK[j * CP + q]);
        }
    }
    __syncthreads();

    if (tid < 128) {
        float* st   = isW ? sWT : sTT;
        float* gdst = isW ? g_W : g_T;
#pragma unroll
        for (int j = 0; j < 64; j++) {
            st[col * CO + j] = rna_tf32(rr_[j]);
            gdst[cb + j * 64 + col] = rr_[j];
        }
    }
    if (tid < 64) {
        g_gam[chunk * 64 + tid] = sGam[tid];
        g_r  [chunk * 64 + tid] = sR[tid];
    }
    __syncthreads();

    // M = gC*I - W^T Ks;  N = T^T Ks   via tf32 mma
    {
        const int lane = tid & 31;
        const int wid  = tid >> 5;
        const int m0 = (wid & 1) * 32;
        const int n0 = (wid >> 1) * 16;
        float accM[2][2][4], accN[2][2][4];
#pragma unroll
        for (int mt = 0; mt < 2; mt++)
#pragma unroll
            for (int nt = 0; nt < 2; nt++)
#pragma unroll
                for (int i = 0; i < 4; i++) { accM[mt][nt][i] = 0.f; accN[mt][nt][i] = 0.f; }
        mma_block64(sWT, sKsT, m0, n0, lane, accM);
        mma_block64(sTT, sKsT, m0, n0, lane, accN);
#pragma unroll
        for (int mt = 0; mt < 2; mt++) {
            const int p0 = m0 + mt * 16 + (lane >> 2);
#pragma unroll
            for (int nt = 0; nt < 2; nt++) {
                const int q0 = n0 + nt * 8 + ((lane & 3) << 1);
#pragma unroll
                for (int half = 0; half < 2; half++) {
                    const int p = p0 + half * 8;
                    const float m0v = ((p == q0)     ? gC : 0.f) - accM[mt][nt][half * 2 + 0];
                    const float m1v = ((p == q0 + 1) ? gC : 0.f) - accM[mt][nt][half * 2 + 1];
                    *(float2*)(g_M + cb + p * 64 + q0) = make_float2(m0v, m1v);
                    *(float2*)(g_N + cb + p * 64 + q0) =
                        make_float2(accN[mt][nt][half * 2 + 0], accN[mt][nt][half * 2 + 1]);
                }
            }
        }
    }
}

__global__ __launch_bounds__(256) void chunk_scan_kernel()
{
    __shared__ float sS[16 * 64];
    __shared__ float sM[64 * 64];
    const int bh = blockIdx.x;
    const int R0 = blockIdx.y * 16;
    const int tid = threadIdx.x;
    const int row = tid >> 4;
    const int tx  = tid & 15;

    for (int idx = tid; idx < 1024; idx += 256) sS[idx] = 0.f;
    __syncthreads();

    for (int c = 0; c < NCHUNK; c++) {
        const long cb = (long)(bh * NCHUNK + c) * 4096;
        for (int idx = tid; idx < 1024; idx += 256)
            g_S0[cb + (long)(R0 + (idx >> 6)) * 64 + (idx & 63)] = sS[idx];
        for (int idx = tid; idx < 4096; idx += 256)
            sM[idx] = g_M[cb + idx];
        __syncthreads();

        float acc[4];
#pragma unroll
        for (int u = 0; u < 4; u++)
            acc[u] = g_N[cb + (long)(R0 + row) * 64 + tx + 16 * u];
        for (int k = 0; k < 64; k++) {
            const float s = sS[row * 64 + k];
#pragma unroll
            for (int u = 0; u < 4; u++)
                acc[u] = fmaf(s, sM[k * 64 + tx + 16 * u], acc[u]);
        }
        __syncthreads();
#pragma unroll
        for (int u = 0; u < 4; u++) sS[row * 64 + tx + 16 * u] = acc[u];
        __syncthreads();
    }
}

// ---- chunk_out: tensor-core (tf32 mma) version ------------------------------
#define CO_SMEM ((6 * 64 * CO + 128) * 4)

__global__ __launch_bounds__(256, 2) void chunk_out_kernel()
{
    extern __shared__ float sm[];
    float* sQg = sm;
    float* sK  = sm + 64 * CO;
    float* sS0 = sm + 2 * 64 * CO;
    float* sW  = sm + 3 * 64 * CO;
    float* sT  = sm + 4 * 64 * CO;
    float* sA  = sm + 5 * 64 * CO;
    float* sGam = sm + 6 * 64 * CO;
    float* sR   = sGam + 64;
    float* sUT  = sK;

    const int chunk = blockIdx.x;
    const int c  = chunk & (NCHUNK - 1);
    const int bh = chunk >> 5;
    const int b = bh >> 4, h = bh & 15;
    const int tid = threadIdx.x;
    const int lane = tid & 31;
    const int wid  = tid >> 5;
    const int m0 = (wid & 1) * 32;
    const int n0 = (wid >> 1) * 16;
    const long rowbase = (long)b * Tt + c * 64;
    const int colbase = h * dh;
    const long cb = (long)chunk * 4096;

    if (tid < 64) {
        sGam[tid] = g_gam[chunk * 64 + tid];
        sR[tid]   = g_r[chunk * 64 + tid];
    }
    __syncthreads();

    for (int idx = tid; idx < 1024; idx += 256) {
        const int row = idx >> 4;
        const int c4  = (idx & 15) << 2;
        const long g = (rowbase + row) * INNER + colbase + c4;
        float4 qv = *(const float4*)(g_Qn + g);
        float4 kv = *(const float4*)(g_Kn + g);
        const float gm = sGam[row];
        sQg[row * CO + c4 + 0] = rna_tf32(qv.x * gm);
        sQg[row * CO + c4 + 1] = rna_tf32(qv.y * gm);
        sQg[row * CO + c4 + 2] = rna_tf32(qv.z * gm);
        sQg[row * CO + c4 + 3] = rna_tf32(qv.w * gm);
        sK [row * CO + c4 + 0] = rna_tf32(kv.x);
        sK [row * CO + c4 + 1] = rna_tf32(kv.y);
        sK [row * CO + c4 + 2] = rna_tf32(kv.z);
        sK [row * CO + c4 + 3] = rna_tf32(kv.w);
    }
    for (int idx = tid; idx < 4096; idx += 256) {
        const int r = idx >> 6, cc = idx & 63;
        sS0[r * CO + cc] = rna_tf32(g_S0[cb + idx]);
        sW [r * CO + cc] = rna_tf32(g_W[cb + idx]);
        sT [r * CO + cc] = g_T[cb + idx];
    }
    __syncthreads();

    // Phase 1: A = tril(diag(gam) Q K^T diag(r))
    {
        float acc[2][2][4];
#pragma unroll
        for (int mt = 0; mt < 2; mt++)
#pragma unroll
            for (int nt = 0; nt < 2; nt++)
#pragma unroll
                for (int i = 0; i < 4; i++) acc[mt][nt][i] = 0.f;
        mma_block64(sQg, sK, m0, n0, lane, acc);
        __syncthreads();
#pragma unroll
        for (int mt = 0; mt < 2; mt++) {
            const int t0r = m0 + mt * 16 + (lane >> 2);
#pragma unroll
            for (int nt = 0; nt < 2; nt++) {
                const int j0 = n0 + nt * 8 + ((lane & 3) << 1);
#pragma unroll
                for (int half = 0; half < 2; half++) {
                    const int t = t0r + half * 8;
                    const float v0 = acc[mt][nt][half * 2 + 0];
                    const float v1 = acc[mt][nt][half * 2 + 1];
                    sA[t * CO + j0]     = (j0     <= t) ? rna_tf32(v0 * sR[j0])     : 0.f;
                    sA[t * CO + j0 + 1] = (j0 + 1 <= t) ? rna_tf32(v1 * sR[j0 + 1]) : 0.f;
                }
            }
        }
    }

    // Phase 2: UT[a][j] = T[j][a] - (S0 W^T)(a,j)
    {
        float acc[2][2][4];
#pragma unroll
        for (int mt = 0; mt < 2; mt++)
#pragma unroll
            for (int nt = 0; nt < 2; nt++)
#pragma unroll
                for (int i = 0; i < 4; i++) acc[mt][nt][i] = 0.f;
        mma_block64(sS0, sW, m0, n0, lane, acc);
        __syncthreads();
#pragma unroll
        for (int mt = 0; mt < 2; mt++) {
            const int a0 = m0 + mt * 16 + (lane >> 2);
#pragma unroll
            for (int nt = 0; nt < 2; nt++) {
                const int j0 = n0 + nt * 8 + ((lane & 3) << 1);
#pragma unroll
                for (int half = 0; half < 2; half++) {
                    const int a = a0 + half * 8;
                    sUT[a * CO + j0]     = rna_tf32(sT[j0 * CO + a]       - acc[mt][nt][half * 2 + 0]);
                    sUT[a * CO + j0 + 1] = rna_tf32(sT[(j0 + 1) * CO + a] - acc[mt][nt][half * 2 + 1]);
                }
            }
        }
    }
    __syncthreads();

    // Phase 3: O = Qg S0^T + A U
    {
        float acc[2][2][4];
#pragma unroll
        for (int mt = 0; mt < 2; mt++)
#pragma unroll
            for (int nt = 0; nt < 2; nt++)
#pragma unroll
                for (int i = 0; i < 4; i++) acc[mt][nt][i] = 0.f;
        mma_block64(sQg, sS0, m0, n0, lane, acc);
        mma_block64(sA, sUT, m0, n0, lane, acc);
#pragma unroll
        for (int mt = 0; mt < 2; mt++) {
            const int t0r = m0 + mt * 16 + (lane >> 2);
#pragma unroll
            for (int nt = 0; nt < 2; nt++) {
                const int a0 = n0 + nt * 8 + ((lane & 3) << 1);
#pragma unroll
                for (int half = 0; half < 2; half++) {
                    const int t = t0r + half * 8;
                    *(float2*)(g_O + (rowbase + t) * INNER + colbase + a0) =
                        make_float2(acc[mt][nt][half * 2 + 0],
                                    acc[mt][nt][half * 2 + 1]);
                }
            }
        }
    }
}

// ---------------- RMS norm + (1+gamma) + gate -> fp16 ------------------------
__global__ __launch_bounds__(256) void rmsgate_kernel(const float* __restrict__ gamma)
{
    const int m = blockIdx.x;
    const int tid = threadIdx.x;
    const long base = (long)m * INNER + tid * 4;
    float4 xv = *(const float4*)(g_O + base);
    float ss = xv.x * xv.x + xv.y * xv.y + xv.z * xv.z + xv.w * xv.w;
    for (int off = 16; off; off >>= 1) ss += __shfl_xor_sync(0xffffffffu, ss, off);
    __shared__ float red[8];
    if ((tid & 31) == 0) red[tid >> 5] = ss;
    __syncthreads();
    float tot = 0.f;
#pragma unroll
    for (int w = 0; w < 8; w++) tot += red[w];
    const float inv = 1.f / sqrtf(tot * (1.f / (float)INNER) + 1e-6f);
    float4 gv = *(const float4*)(g_Xg + base);
    float4 gm = *(const float4*)(gamma + tid * 4);
    __half2 h[2];
    h[0] = __floats2half2_rn(xv.x * inv * (1.f + gm.x) * gv.x,
                             xv.y * inv * (1.f + gm.y) * gv.y);
    h[1] = __floats2half2_rn(xv.z * inv * (1.f + gm.z) * gv.z,
                             xv.w * inv * (1.f + gm.w) * gv.w);
    *(uint2*)(g_Yh + base) = *(const uint2*)h;
}

// ---------------- launch -----------------------------------------------------
extern "C" void kernel_launch(void* const* d_in, const int* in_sizes, int n_in,
                              void* d_out, int out_size)
{
    const float* x    = (const float*)d_in[0];
    const float* Wq   = (const float*)d_in[1];
    const float* Wk   = (const float*)d_in[2];
    const float* Wv   = (const float*)d_in[3];
    const float* Wa   = (const float*)d_in[4];
    const float* ba   = (const float*)d_in[5];
    const float* Wb   = (const float*)d_in[6];
    const float* bb   = (const float*)d_in[7];
    const float* Wg   = (const float*)d_in[8];
    const float* Wo   = (const float*)d_in[9];
    const float* cq_w = (const float*)d_in[10];
    const float* cq_b = (const float*)d_in[11];
    const float* ck_w = (const float*)d_in[12];
    const float* ck_b = (const float*)d_in[13];
    const float* cv_w = (const float*)d_in[14];
    const float* cv_b = (const float*)d_in[15];
    const float* gamma= (const float*)d_in[16];
    float* out = (float*)d_out;

    cudaFuncSetAttribute(chunk_prep_kernel,
                         cudaFuncAttributeMaxDynamicSharedMemorySize, PREP_SMEM);
    cudaFuncSetAttribute(chunk_out_kernel,
                         cudaFuncAttributeMaxDynamicSharedMemorySize, CO_SMEM);
    cudaFuncSetAttribute(proj_gemm_kernel,
                         cudaFuncAttributeMaxDynamicSharedMemorySize, GSMEM);
    cudaFuncSetAttribute(out_gemm_kernel,
                         cudaFuncAttributeMaxDynamicSharedMemorySize, GSMEM);

    cvt_kernel<<<Mrows * Dd / 2048, 256>>>(x);
    wtrans_kernel<<<dim3(32, 32, 5), 256>>>(Wq, Wk, Wv, Wg, Wo);
    proj_gemm_kernel<<<dim3(INNER / 128, Mrows / 128, 4), 128, GSMEM>>>();
    convab_kernel<<<dim3(Mrows / 8, 4, 4), 128>>>(x, cq_w, cq_b, ck_w, ck_b,
                                                  cv_w, cv_b, Wa, ba, Wb, bb);
    chunk_prep_kernel<<<1024, 256, PREP_SMEM>>>();
    chunk_scan_kernel<<<dim3(Bz * Hh, 4), 256>>>();
    chunk_out_kernel<<<1024, 256, CO_SMEM>>>();
    rmsgate_kernel<<<Mrows, 256>>>(gamma);
    out_gemm_kernel<<<dim3(Dd / 128, Mrows / 128), 128, GSMEM>>>(out);
}

// round 13
// speedup vs baseline: 1.2553x; 1.0449x over previous
#include <cuda_runtime.h>
#include <cuda_fp16.h>
#include <math.h>
#include <stdint.h>

// Problem constants
#define Bz 2
#define Tt 2048
#define Dd 1024
#define Hh 16
#define dh 64
#define INNER 1024
#define Mrows 4096   // B*T
#define NCHUNK 32
#define CP 65        // padded stride for 64x64 smem tiles (SIMT kernels)
#define CO 68        // padded stride for mma tiles

// ---------------- scratch ----------------------------------------------------
__device__ float g_Xq[Mrows * INNER];
__device__ float g_Xk[Mrows * INNER];
__device__ float g_Xv[Mrows * INNER];
__device__ float g_Xg[Mrows * INNER];
__device__ float g_Qn[Mrows * INNER];
__device__ float g_Kn[Mrows * INNER];
__device__ float g_Vv[Mrows * INNER];
__device__ float g_AB[Mrows * 32];
__device__ float g_O [Mrows * INNER];
__device__ __half g_xh[Mrows * Dd];        // fp16 x
__device__ __half g_Wh[5 * Dd * INNER];    // fp16 TRANSPOSED weights [n][k]
__device__ __half g_Yh[Mrows * INNER];     // fp16 rms*gamma*gate
__device__ float g_T [1024 * 4096];
__device__ float g_W [1024 * 4096];
__device__ float g_M [1024 * 4096];
__device__ float g_N [1024 * 4096];
__device__ float g_S0[1024 * 4096];
__device__ float g_gam[1024 * 64];
__device__ float g_r  [1024 * 64];

// ---------------- helpers ----------------------------------------------------
__device__ __forceinline__ unsigned cvt_tf32(float f) {
    unsigned u;
    asm("cvt.rna.tf32.f32 %0, %1;" : "=r"(u) : "f"(f));
    return u;
}
__device__ __forceinline__ float rna_tf32(float f) {
    return __uint_as_float(cvt_tf32(f));
}
__device__ __forceinline__ uint32_t smem_u32(const void* p) {
    uint32_t a;
    asm("{ .reg .u64 t; cvta.to.shared.u64 t, %1; cvt.u32.u64 %0, t; }"
        : "=r"(a) : "l"(p));
    return a;
}
__device__ __forceinline__ void cp16(uint32_t saddr, const void* gptr) {
    asm volatile("cp.async.cg.shared.global [%0], [%1], 16;" :: "r"(saddr), "l"(gptr));
}
#define CP_COMMIT() asm volatile("cp.async.commit_group;" ::: "memory")

__device__ __forceinline__ void mma_tf32(float* d, unsigned a0, unsigned a1,
                                         unsigned a2, unsigned a3,
                                         unsigned b0, unsigned b1) {
    asm("mma.sync.aligned.m16n8k8.row.col.f32.tf32.tf32.f32 "
        "{%0,%1,%2,%3}, {%4,%5,%6,%7}, {%8,%9}, {%0,%1,%2,%3};\n"
        : "+f"(d[0]), "+f"(d[1]), "+f"(d[2]), "+f"(d[3])
        : "r"(a0), "r"(a1), "r"(a2), "r"(a3), "r"(b0), "r"(b1));
}

__device__ __forceinline__ void mma_f16(float* d, unsigned a0, unsigned a1,
                                        unsigned a2, unsigned a3,
                                        unsigned b0, unsigned b1) {
    asm("mma.sync.aligned.m16n8k16.row.col.f32.f16.f16.f32 "
        "{%0,%1,%2,%3}, {%4,%5,%6,%7}, {%8,%9}, {%0,%1,%2,%3};\n"
        : "+f"(d[0]), "+f"(d[1]), "+f"(d[2]), "+f"(d[3])
        : "r"(a0), "r"(a1), "r"(a2), "r"(a3), "r"(b0), "r"(b1));
}

// 64x64x64 tf32 mma block: acc[m][n] += sum_k As_[m][k]*Bs_[n][k], CO stride.
__device__ __forceinline__ void mma_block64(const float* __restrict__ As_,
                                            const float* __restrict__ Bs_,
                                            int m0, int n0, int lane,
                                            float acc[2][2][4])
{
#pragma unroll
    for (int k8 = 0; k8 < 64; k8 += 8) {
        const int kk0 = k8 + (lane & 3);
        const int kk1 = kk0 + 4;
        unsigned af[2][4], bf[2][2];
#pragma unroll
        for (int mt = 0; mt < 2; mt++) {
            const int r0 = m0 + mt * 16 + (lane >> 2);
            af[mt][0] = __float_as_uint(As_[r0 * CO + kk0]);
            af[mt][1] = __float_as_uint(As_[(r0 + 8) * CO + kk0]);
            af[mt][2] = __float_as_uint(As_[r0 * CO + kk1]);
            af[mt][3] = __float_as_uint(As_[(r0 + 8) * CO + kk1]);
        }
#pragma unroll
        for (int nt = 0; nt < 2; nt++) {
            const int n = n0 + nt * 8 + (lane >> 2);
            bf[nt][0] = __float_as_uint(Bs_[n * CO + kk0]);
            bf[nt][1] = __float_as_uint(Bs_[n * CO + kk1]);
        }
#pragma unroll
        for (int mt = 0; mt < 2; mt++)
#pragma unroll
            for (int nt = 0; nt < 2; nt++)
                mma_tf32(acc[mt][nt], af[mt][0], af[mt][1], af[mt][2], af[mt][3],
                         bf[nt][0], bf[nt][1]);
    }
}

// ---------------- fp16 GEMM, 128x128 tile, cp.async 3-stage pipeline ---------
#define PADH 24
#define HST (128 * PADH)
#define GSMEM (6 * HST * 2)

__device__ __forceinline__ void hgemm128(const __half* __restrict__ A,
                                         const __half* __restrict__ Bt,
                                         float* __restrict__ C,
                                         int N, int bm, int bn,
                                         bool do_silu)
{
    extern __shared__ __half smh[];

    const int tid  = threadIdx.x;
    const int lane = tid & 31;
    const int wid  = tid >> 5;
    const int warpM = (wid & 1) * 64;
    const int warpN = (wid >> 1) * 64;

    float acc[4][8][4];
#pragma unroll
    for (int mt = 0; mt < 4; mt++)
#pragma unroll
        for (int nt = 0; nt < 8; nt++)
#pragma unroll
            for (int i = 0; i < 4; i++) acc[mt][nt][i] = 0.f;

    const uint32_t asu = smem_u32(smh);
    const uint32_t bsu = asu + 3 * HST * 2;

    auto load_stage = [&](int kt, int st) {
        const int k0 = kt << 4;
        const uint32_t sa = asu + st * (HST * 2);
        const uint32_t sb = bsu + st * (HST * 2);
#pragma unroll
        for (int i = 0; i < 2; i++) {
            const int idx = tid + i * 128;
            const int row = idx >> 1;
            const int hf  = (idx & 1) * 8;
            cp16(sa + (row * PADH + hf) * 2, A  + (long)(bm + row) * 1024 + k0 + hf);
            cp16(sb + (row * PADH + hf) * 2, Bt + (long)(bn + row) * 1024 + k0 + hf);
        }
        CP_COMMIT();
    };

    load_stage(0, 0);
    load_stage(1, 1);
    load_stage(2, 2);

    const int fr = lane >> 2;
    const int kp = (lane & 3) * 2;

    for (int kt = 0; kt < 64; kt++) {
        const int st = kt - (kt / 3) * 3;
        if (kt <= 61)      asm volatile("cp.async.wait_group 2;" ::: "memory");
        else if (kt == 62) asm volatile("cp.async.wait_group 1;" ::: "memory");
        else               asm volatile("cp.async.wait_group 0;" ::: "memory");
        __syncthreads();

        const __half* as = smh + st * HST;
        const __half* bs = smh + 3 * HST + st * HST;

        unsigned af[4][4], bf[8][2];
#pragma unroll
        for (int mt = 0; mt < 4; mt++) {
            const int r0 = warpM + mt * 16 + fr;
            af[mt][0] = *(const unsigned*)(as + r0 * PADH + kp);
            af[mt][1] = *(const unsigned*)(as + (r0 + 8) * PADH + kp);
            af[mt][2] = *(const unsigned*)(as + r0 * PADH + kp + 8);
            af[mt][3] = *(const unsigned*)(as + (r0 + 8) * PADH + kp + 8);
        }
#pragma unroll
        for (int nt = 0; nt < 8; nt++) {
            const int n = warpN + nt * 8 + fr;
            bf[nt][0] = *(const unsigned*)(bs + n * PADH + kp);
            bf[nt][1] = *(const unsigned*)(bs + n * PADH + kp + 8);
        }
#pragma unroll
        for (int mt = 0; mt < 4; mt++)
#pragma unroll
            for (int nt = 0; nt < 8; nt++)
                mma_f16(acc[mt][nt], af[mt][0], af[mt][1], af[mt][2], af[mt][3],
                        bf[nt][0], bf[nt][1]);

        __syncthreads();
        if (kt + 3 < 64) load_stage(kt + 3, st);
    }

#pragma unroll
    for (int mt = 0; mt < 4; mt++) {
        const int r0 = bm + warpM + mt * 16 + (lane >> 2);
#pragma unroll
        for (int nt = 0; nt < 8; nt++) {
            const int c = bn + warpN + nt * 8 + ((lane & 3) << 1);
            float v0 = acc[mt][nt][0], v1 = acc[mt][nt][1];
            float v2 = acc[mt][nt][2], v3 = acc[mt][nt][3];
            if (do_silu) {
                v0 = v0 / (1.f + expf(-v0));
                v1 = v1 / (1.f + expf(-v1));
                v2 = v2 / (1.f + expf(-v2));
                v3 = v3 / (1.f + expf(-v3));
            }
            *(float2*)(C + (long)r0 * N + c)       = make_float2(v0, v1);
            *(float2*)(C + (long)(r0 + 8) * N + c) = make_float2(v2, v3);
        }
    }
}

__global__ __launch_bounds__(128) void proj_gemm_kernel()
{
    const int z = blockIdx.z;
    const __half* W = g_Wh + (long)z * (Dd * INNER);
    float* O;
    bool silu = false;
    switch (z) {
        case 0:  O = g_Xq; break;
        case 1:  O = g_Xk; break;
        case 2:  O = g_Xv; break;
        default: O = g_Xg; silu = true; break;
    }
    hgemm128(g_xh, W, O, INNER, blockIdx.y * 128, blockIdx.x * 128, silu);
}

__global__ __launch_bounds__(128) void out_gemm_kernel(float* __restrict__ out)
{
    hgemm128(g_Yh, g_Wh + 4L * Dd * INNER, out, Dd,
             blockIdx.y * 128, blockIdx.x * 128, false);
}

// ---------------- pre-passes -------------------------------------------------
__global__ __launch_bounds__(256) void cvt_kernel(const float* __restrict__ x)
{
    const long i = ((long)blockIdx.x * 256 + threadIdx.x) * 8;
    float4 v0 = *(const float4*)(x + i);
    float4 v1 = *(const float4*)(x + i + 4);
    __half2 h[4];
    h[0] = __floats2half2_rn(v0.x, v0.y);
    h[1] = __floats2half2_rn(v0.z, v0.w);
    h[2] = __floats2half2_rn(v1.x, v1.y);
    h[3] = __floats2half2_rn(v1.z, v1.w);
    *(uint4*)(g_xh + i) = *(const uint4*)h;
}

__global__ __launch_bounds__(256) void wtrans_kernel(
    const float* __restrict__ Wq, const float* __restrict__ Wk,
    const float* __restrict__ Wv, const float* __restrict__ Wg,
    const float* __restrict__ Wo)
{
    const float* W;
    switch (blockIdx.z) {
        case 0: W = Wq; break;
        case 1: W = Wk; break;
        case 2: W = Wv; break;
        case 3: W = Wg; break;
        default: W = Wo; break;
    }
    __half* Out = g_Wh + (long)blockIdx.z * (Dd * INNER);
    __shared__ float t[32][33];
    const int tx = threadIdx.x & 31;
    const int ty = threadIdx.x >> 5;
    const int bx = blockIdx.x * 32;
    const int by = blockIdx.y * 32;
#pragma unroll
    for (int i = 0; i < 4; i++)
        t[ty + i * 8][tx] = W[(long)(by + ty + i * 8) * 1024 + bx + tx];
    __syncthreads();
#pragma unroll
    for (int i = 0; i < 4; i++)
        Out[(long)(bx + ty + i * 8) * 1024 + by + tx] = __float2half_rn(t[tx][ty + i * 8]);
}

// ---------------- conv (no shared memory — occupancy-unconstrained) ----------
__global__ __launch_bounds__(128) void conv_kernel(
    const float* __restrict__ cq_w, const float* __restrict__ cq_b,
    const float* __restrict__ ck_w, const float* __restrict__ ck_b,
    const float* __restrict__ cv_w, const float* __restrict__ cv_b)
{
    const float* Xin; float* Out; const float* cw; const float* cb; bool donorm;
    switch (blockIdx.z) {
        case 0:  Xin = g_Xq; Out = g_Qn; cw = cq_w; cb = cq_b; donorm = true;  break;
        case 1:  Xin = g_Xk; Out = g_Kn; cw = ck_w; cb = ck_b; donorm = true;  break;
        default: Xin = g_Xv; Out = g_Vv; cw = cv_w; cb = cv_b; donorm = false; break;
    }
    const int bt0 = blockIdx.x * 8;
    const int t0  = bt0 & (Tt - 1);
    const int lane = threadIdx.x & 31;
    const int wid  = threadIdx.x >> 5;
    const int h = blockIdx.y * 4 + wid;
    const int c0 = h * 64 + lane;

    float x0[11], x1[11];
#pragma unroll
    for (int i = 0; i < 11; i++) {
        const int t = t0 - 3 + i;
        if (t < 0) { x0[i] = 0.f; x1[i] = 0.f; }
        else {
            const long g = (long)(bt0 - t0 + t) * INNER + c0;
            x0[i] = Xin[g];
            x1[i] = Xin[g + 32];
        }
    }
    float w0[4], w1[4];
#pragma unroll
    for (int k = 0; k < 4; k++) {
        w0[k] = cw[c0 * 4 + k];
        w1[k] = cw[(c0 + 32) * 4 + k];
    }
    const float b0 = cb[c0], b1 = cb[c0 + 32];

#pragma unroll
    for (int tt = 0; tt < 8; tt++) {
        float a0 = b0, a1 = b1;
#pragma unroll
        for (int k = 0; k < 4; k++) {
            a0 = fmaf(x0[tt + k], w0[k], a0);
            a1 = fmaf(x1[tt + k], w1[k], a1);
        }
        float s0 = a0 / (1.f + expf(-a0));
        float s1 = a1 / (1.f + expf(-a1));
        float ss = s0 * s0 + s1 * s1;
        ss += __shfl_xor_sync(0xffffffffu, ss, 16);
        ss += __shfl_xor_sync(0xffffffffu, ss, 8);
        ss += __shfl_xor_sync(0xffffffffu, ss, 4);
        ss += __shfl_xor_sync(0xffffffffu, ss, 2);
        ss += __shfl_xor_sync(0xffffffffu, ss, 1);
        if (donorm) {
            const float inv = 1.f / fmaxf(sqrtf(ss), 1e-12f);
            s0 *= inv; s1 *= inv;
        }
        const long g = (long)(bt0 + tt) * INNER + c0;
        Out[g] = s0;
        Out[g + 32] = s1;
    }
}

// ---------------- alpha/beta mini-GEMM (own kernel, smem OK) -----------------
__global__ __launch_bounds__(128) void ab_kernel(
    const float* __restrict__ x,
    const float* __restrict__ Wa, const float* __restrict__ ba,
    const float* __restrict__ Wb, const float* __restrict__ bb)
{
    __shared__ float s_ab[32 * 65 + 64 * 33];
    const int blk = blockIdx.x;
    const int tid = threadIdx.x;
    float* xs = s_ab;
    float* ws = s_ab + 32 * 65;
    const int mrow = tid >> 2;
    const int ogrp = tid & 3;

    float acc[8];
#pragma unroll
    for (int j = 0; j < 8; j++) acc[j] = 0.f;

    for (int k0 = 0; k0 < Dd; k0 += 64) {
#pragma unroll
        for (int i = 0; i < 4; i++) {
            const int idx = tid + i * 128;
            const int row = idx >> 4;
            const int c4  = (idx & 15) << 2;
            float4 v = *(const float4*)(x + (long)(blk * 32 + row) * Dd + k0 + c4);
            xs[row * 65 + c4 + 0] = v.x;
            xs[row * 65 + c4 + 1] = v.y;
            xs[row * 65 + c4 + 2] = v.z;
            xs[row * 65 + c4 + 3] = v.w;
        }
#pragma unroll
        for (int i = 0; i < 16; i++) {
            const int idx = tid + i * 128;
            const int row = idx >> 5;
            const int col = idx & 31;
            ws[row * 33 + col] = (col < 16) ? Wa[(k0 + row) * Hh + col]
                                            : Wb[(k0 + row) * Hh + col - 16];
        }
        __syncthreads();
#pragma unroll 8
        for (int k = 0; k < 64; k++) {
            const float xv = xs[mrow * 65 + k];
#pragma unroll
            for (int j = 0; j < 8; j++)
                acc[j] = fmaf(xv, ws[k * 33 + ogrp * 8 + j], acc[j]);
        }
        __syncthreads();
    }
#pragma unroll
    for (int j = 0; j < 8; j++) {
        const int o = ogrp * 8 + j;
        const float bias = (o < 16) ? ba[o] : bb[o - 16];
        g_AB[(long)(blk * 32 + mrow) * 32 + o] =
            1.f / (1.f + expf(-(acc[j] + bias)));
    }
}

// ============== chunked delta-rule scan ======================================
// prep: L + solve in fp32; M,N via tf32 mma (error is decayed by gC ~ 3e-4).
#define PREP_SMEM ((3 * 64 * CP + 3 * 64 * CO + 128) * 4)

__global__ __launch_bounds__(256, 2) void chunk_prep_kernel()
{
    extern __shared__ float sm[];
    float* sK   = sm;                         // [64][CP] raw K
    float* sV   = sm + 64 * CP;               // [64][CP] raw V
    float* sL   = sm + 2 * 64 * CP;           // [64][CP] L
    float* sWT  = sm + 3 * 64 * CP;           // [64][CO] W^T (rounded)
    float* sTT  = sWT + 64 * CO;              // [64][CO] T^T (rounded)
    float* sKsT = sWT + 2 * 64 * CO;          // [64][CO] (gC r K)^T (rounded)
    float* sGam = sWT + 3 * 64 * CO;
    float* sR   = sGam + 64;

    const int chunk = blockIdx.x;
    const int c  = chunk & (NCHUNK - 1);
    const int bh = chunk >> 5;
    const int b = bh >> 4, h = bh & 15;
    const int tid = threadIdx.x;
    const long rowbase = (long)b * Tt + c * 64;
    const int colbase = h * dh;
    const long cb = (long)chunk * 4096;

    for (int idx = tid; idx < 1024; idx += 256) {
        const int row = idx >> 4;
        const int c4  = (idx & 15) << 2;
        const long g = (rowbase + row) * INNER + colbase + c4;
        float4 kv = *(const float4*)(g_Kn + g);
        float4 vv = *(const float4*)(g_Vv + g);
        sK[row * CP + c4 + 0] = kv.x; sK[row * CP + c4 + 1] = kv.y;
        sK[row * CP + c4 + 2] = kv.z; sK[row * CP + c4 + 3] = kv.w;
        sV[row * CP + c4 + 0] = vv.x; sV[row * CP + c4 + 1] = vv.y;
        sV[row * CP + c4 + 2] = vv.z; sV[row * CP + c4 + 3] = vv.w;
    }
    if (tid < 64) {
        sGam[tid] = g_AB[(rowbase + tid) * 32 + h];
        sR[tid]   = g_AB[(rowbase + tid) * 32 + 16 + h];
    }
    __syncthreads();
    if (tid == 0) {
        float p = 1.f;
        for (int i = 0; i < 64; i++) { p *= sGam[i]; sGam[i] = p; }
    }
    __syncthreads();
    if (tid < 64) sR[tid] = sR[tid] / sGam[tid];
    __syncthreads();

    const int ty = tid >> 4, tx = tid & 15;

    // L[j][i] = (i<j) ? gam[j]*r[i]*<k_i,k_j> : 0   (fp32 SIMT)
    {
        float acc[4][4];
#pragma unroll
        for (int v = 0; v < 4; v++)
#pragma unroll
            for (int u = 0; u < 4; u++) acc[v][u] = 0.f;
        for (int k = 0; k < 64; k++) {
            float a[4], bb[4];
#pragma unroll
            for (int v = 0; v < 4; v++) a[v]  = sK[(ty + 16 * v) * CP + k];
#pragma unroll
            for (int u = 0; u < 4; u++) bb[u] = sK[(tx + 16 * u) * CP + k];
#pragma unroll
            for (int v = 0; v < 4; v++)
#pragma unroll
                for (int u = 0; u < 4; u++)
                    acc[v][u] = fmaf(a[v], bb[u], acc[v][u]);
        }
#pragma unroll
        for (int v = 0; v < 4; v++)
#pragma unroll
            for (int u = 0; u < 4; u++) {
                const int j = ty + 16 * v, i = tx + 16 * u;
                sL[j * CP + i] = (i < j) ? acc[v][u] * sGam[j] * sR[i] : 0.f;
            }
        __syncthreads();
    }

    // solve (tid<128, fp32, in registers)  ||  build Ks^T (tid>=128)
    const float gC = sGam[63];
    float rr_[64];
    const int col = tid & 63;
    const int isW = (tid >> 6) & 1;
    if (tid < 128) {
#pragma unroll
        for (int j = 0; j < 64; j++)
            rr_[j] = isW ? sGam[j] * sK[j * CP + col] : sV[j * CP + col];
#pragma unroll
        for (int j = 0; j < 64; j++) {
            const float xj = rr_[j];
#pragma unroll
            for (int i = j + 1; i < 64; i++)
                rr_[i] -= sL[i * CP + j] * xj;
        }
    } else {
        const int t2 = tid - 128;
        for (int idx = t2; idx < 4096; idx += 128) {
            const int j = idx & 63, q = idx >> 6;
            sKsT[q * CO + j] = rna_tf32(gC * sR[j] * sK[j * CP + q]);
        }
    }
    __syncthreads();

    if (tid < 128) {
        float* st   = isW ? sWT : sTT;
        float* gdst = isW ? g_W : g_T;
#pragma unroll
        for (int j = 0; j < 64; j++) {
            st[col * CO + j] = rna_tf32(rr_[j]);
            gdst[cb + j * 64 + col] = rr_[j];
        }
    }
    if (tid < 64) {
        g_gam[chunk * 64 + tid] = sGam[tid];
        g_r  [chunk * 64 + tid] = sR[tid];
    }
    __syncthreads();

    // M = gC*I - W^T Ks;  N = T^T Ks   via tf32 mma
    {
        const int lane = tid & 31;
        const int wid  = tid >> 5;
        const int m0 = (wid & 1) * 32;
        const int n0 = (wid >> 1) * 16;
        float accM[2][2][4], accN[2][2][4];
#pragma unroll
        for (int mt = 0; mt < 2; mt++)
#pragma unroll
            for (int nt = 0; nt < 2; nt++)
#pragma unroll
                for (int i = 0; i < 4; i++) { accM[mt][nt][i] = 0.f; accN[mt][nt][i] = 0.f; }
        mma_block64(sWT, sKsT, m0, n0, lane, accM);
        mma_block64(sTT, sKsT, m0, n0, lane, accN);
#pragma unroll
        for (int mt = 0; mt < 2; mt++) {
            const int p0 = m0 + mt * 16 + (lane >> 2);
#pragma unroll
            for (int nt = 0; nt < 2; nt++) {
                const int q0 = n0 + nt * 8 + ((lane & 3) << 1);
#pragma unroll
                for (int half = 0; half < 2; half++) {
                    const int p = p0 + half * 8;
                    const float m0v = ((p == q0)     ? gC : 0.f) - accM[mt][nt][half * 2 + 0];
                    const float m1v = ((p == q0 + 1) ? gC : 0.f) - accM[mt][nt][half * 2 + 1];
                    *(float2*)(g_M + cb + p * 64 + q0) = make_float2(m0v, m1v);
                    *(float2*)(g_N + cb + p * 64 + q0) =
                        make_float2(accN[mt][nt][half * 2 + 0], accN[mt][nt][half * 2 + 1]);
                }
            }
        }
    }
}

__global__ __launch_bounds__(256) void chunk_scan_kernel()
{
    __shared__ float sS[16 * 64];
    __shared__ float sM[64 * 64];
    const int bh = blockIdx.x;
    const int R0 = blockIdx.y * 16;
    const int tid = threadIdx.x;
    const int row = tid >> 4;
    const int tx  = tid & 15;

    for (int idx = tid; idx < 1024; idx += 256) sS[idx] = 0.f;
    __syncthreads();

    for (int c = 0; c < NCHUNK; c++) {
        const long cb = (long)(bh * NCHUNK + c) * 4096;
        for (int idx = tid; idx < 1024; idx += 256)
            g_S0[cb + (long)(R0 + (idx >> 6)) * 64 + (idx & 63)] = sS[idx];
        for (int idx = tid; idx < 4096; idx += 256)
            sM[idx] = g_M[cb + idx];
        __syncthreads();

        float acc[4];
#pragma unroll
        for (int u = 0; u < 4; u++)
            acc[u] = g_N[cb + (long)(R0 + row) * 64 + tx + 16 * u];
        for (int k = 0; k < 64; k++) {
            const float s = sS[row * 64 + k];
#pragma unroll
            for (int u = 0; u < 4; u++)
                acc[u] = fmaf(s, sM[k * 64 + tx + 16 * u], acc[u]);
        }
        __syncthreads();
#pragma unroll
        for (int u = 0; u < 4; u++) sS[row * 64 + tx + 16 * u] = acc[u];
        __syncthreads();
    }
}

// ---- chunk_out: tensor-core (tf32 mma) version ------------------------------
#define CO_SMEM ((6 * 64 * CO + 128) * 4)

__global__ __launch_bounds__(256, 2) void chunk_out_kernel()
{
    extern __shared__ float sm[];
    float* sQg = sm;
    float* sK  = sm + 64 * CO;
    float* sS0 = sm + 2 * 64 * CO;
    float* sW  = sm + 3 * 64 * CO;
    float* sT  = sm + 4 * 64 * CO;
    float* sA  = sm + 5 * 64 * CO;
    float* sGam = sm + 6 * 64 * CO;
    float* sR   = sGam + 64;
    float* sUT  = sK;

    const int chunk = blockIdx.x;
    const int c  = chunk & (NCHUNK - 1);
    const int bh = chunk >> 5;
    const int b = bh >> 4, h = bh & 15;
    const int tid = threadIdx.x;
    const int lane = tid & 31;
    const int wid  = tid >> 5;
    const int m0 = (wid & 1) * 32;
    const int n0 = (wid >> 1) * 16;
    const long rowbase = (long)b * Tt + c * 64;
    const int colbase = h * dh;
    const long cb = (long)chunk * 4096;

    if (tid < 64) {
        sGam[tid] = g_gam[chunk * 64 + tid];
        sR[tid]   = g_r[chunk * 64 + tid];
    }
    __syncthreads();

    for (int idx = tid; idx < 1024; idx += 256) {
        const int row = idx >> 4;
        const int c4  = (idx & 15) << 2;
        const long g = (rowbase + row) * INNER + colbase + c4;
        float4 qv = *(const float4*)(g_Qn + g);
        float4 kv = *(const float4*)(g_Kn + g);
        const float gm = sGam[row];
        sQg[row * CO + c4 + 0] = rna_tf32(qv.x * gm);
        sQg[row * CO + c4 + 1] = rna_tf32(qv.y * gm);
        sQg[row * CO + c4 + 2] = rna_tf32(qv.z * gm);
        sQg[row * CO + c4 + 3] = rna_tf32(qv.w * gm);
        sK [row * CO + c4 + 0] = rna_tf32(kv.x);
        sK [row * CO + c4 + 1] = rna_tf32(kv.y);
        sK [row * CO + c4 + 2] = rna_tf32(kv.z);
        sK [row * CO + c4 + 3] = rna_tf32(kv.w);
    }
    for (int idx = tid; idx < 4096; idx += 256) {
        const int r = idx >> 6, cc = idx & 63;
        sS0[r * CO + cc] = rna_tf32(g_S0[cb + idx]);
        sW [r * CO + cc] = rna_tf32(g_W[cb + idx]);
        sT [r * CO + cc] = g_T[cb + idx];
    }
    __syncthreads();

    // Phase 1: A = tril(diag(gam) Q K^T diag(r))
    {
        float acc[2][2][4];
#pragma unroll
        for (int mt = 0; mt < 2; mt++)
#pragma unroll
            for (int nt = 0; nt < 2; nt++)
#pragma unroll
                for (int i = 0; i < 4; i++) acc[mt][nt][i] = 0.f;
        mma_block64(sQg, sK, m0, n0, lane, acc);
        __syncthreads();
#pragma unroll
        for (int mt = 0; mt < 2; mt++) {
            const int t0r = m0 + mt * 16 + (lane >> 2);
#pragma unroll
            for (int nt = 0; nt < 2; nt++) {
                const int j0 = n0 + nt * 8 + ((lane & 3) << 1);
#pragma unroll
                for (int half = 0; half < 2; half++) {
                    const int t = t0r + half * 8;
                    const float v0 = acc[mt][nt][half * 2 + 0];
                    const float v1 = acc[mt][nt][half * 2 + 1];
                    sA[t * CO + j0]     = (j0     <= t) ? rna_tf32(v0 * sR[j0])     : 0.f;
                    sA[t * CO + j0 + 1] = (j0 + 1 <= t) ? rna_tf32(v1 * sR[j0 + 1]) : 0.f;
                }
            }
        }
    }

    // Phase 2: UT[a][j] = T[j][a] - (S0 W^T)(a,j)
    {
        float acc[2][2][4];
#pragma unroll
        for (int mt = 0; mt < 2; mt++)
#pragma unroll
            for (int nt = 0; nt < 2; nt++)
#pragma unroll
                for (int i = 0; i < 4; i++) acc[mt][nt][i] = 0.f;
        mma_block64(sS0, sW, m0, n0, lane, acc);
        __syncthreads();
#pragma unroll
        for (int mt = 0; mt < 2; mt++) {
            const int a0 = m0 + mt * 16 + (lane >> 2);
#pragma unroll
            for (int nt = 0; nt < 2; nt++) {
                const int j0 = n0 + nt * 8 + ((lane & 3) << 1);
#pragma unroll
                for (int half = 0; half < 2; half++) {
                    const int a = a0 + half * 8;
                    sUT[a * CO + j0]     = rna_tf32(sT[j0 * CO + a]       - acc[mt][nt][half * 2 + 0]);
                    sUT[a * CO + j0 + 1] = rna_tf32(sT[(j0 + 1) * CO + a] - acc[mt][nt][half * 2 + 1]);
                }
            }
        }
    }
    __syncthreads();

    // Phase 3: O = Qg S0^T + A U
    {
        float acc[2][2][4];
#pragma unroll
        for (int mt = 0; mt < 2; mt++)
#pragma unroll
            for (int nt = 0; nt < 2; nt++)
#pragma unroll
                for (int i = 0; i < 4; i++) acc[mt][nt][i] = 0.f;
        mma_block64(sQg, sS0, m0, n0, lane, acc);
        mma_block64(sA, sUT, m0, n0, lane, acc);
#pragma unroll
        for (int mt = 0; mt < 2; mt++) {
            const int t0r = m0 + mt * 16 + (lane >> 2);
#pragma unroll
            for (int nt = 0; nt < 2; nt++) {
                const int a0 = n0 + nt * 8 + ((lane & 3) << 1);
#pragma unroll
                for (int half = 0; half < 2; half++) {
                    const int t = t0r + half * 8;
                    *(float2*)(g_O + (rowbase + t) * INNER + colbase + a0) =
                        make_float2(acc[mt][nt][half * 2 + 0],
                                    acc[mt][nt][half * 2 + 1]);
                }
            }
        }
    }
}

// ---------------- RMS norm + (1+gamma) + gate -> fp16 ------------------------
__global__ __launch_bounds__(256) void rmsgate_kernel(const float* __restrict__ gamma)
{
    const int m = blockIdx.x;
    const int tid = threadIdx.x;
    const long base = (long)m * INNER + tid * 4;
    float4 xv = *(const float4*)(g_O + base);
    float ss = xv.x * xv.x + xv.y * xv.y + xv.z * xv.z + xv.w * xv.w;
    for (int off = 16; off; off >>= 1) ss += __shfl_xor_sync(0xffffffffu, ss, off);
    __shared__ float red[8];
    if ((tid & 31) == 0) red[tid >> 5] = ss;
    __syncthreads();
    float tot = 0.f;
#pragma unroll
    for (int w = 0; w < 8; w++) tot += red[w];
    const float inv = 1.f / sqrtf(tot * (1.f / (float)INNER) + 1e-6f);
    float4 gv = *(const float4*)(g_Xg + base);
    float4 gm = *(const float4*)(gamma + tid * 4);
    __half2 h[2];
    h[0] = __floats2half2_rn(xv.x * inv * (1.f + gm.x) * gv.x,
                             xv.y * inv * (1.f + gm.y) * gv.y);
    h[1] = __floats2half2_rn(xv.z * inv * (1.f + gm.z) * gv.z,
                             xv.w * inv * (1.f + gm.w) * gv.w);
    *(uint2*)(g_Yh + base) = *(const uint2*)h;
}

// ---------------- launch -----------------------------------------------------
extern "C" void kernel_launch(void* const* d_in, const int* in_sizes, int n_in,
                              void* d_out, int out_size)
{
    const float* x    = (const float*)d_in[0];
    const float* Wq   = (const float*)d_in[1];
    const float* Wk   = (const float*)d_in[2];
    const float* Wv   = (const float*)d_in[3];
    const float* Wa   = (const float*)d_in[4];
    const float* ba   = (const float*)d_in[5];
    const float* Wb   = (const float*)d_in[6];
    const float* bb   = (const float*)d_in[7];
    const float* Wg   = (const float*)d_in[8];
    const float* Wo   = (const float*)d_in[9];
    const float* cq_w = (const float*)d_in[10];
    const float* cq_b = (const float*)d_in[11];
    const float* ck_w = (const float*)d_in[12];
    const float* ck_b = (const float*)d_in[13];
    const float* cv_w = (const float*)d_in[14];
    const float* cv_b = (const float*)d_in[15];
    const float* gamma= (const float*)d_in[16];
    float* out = (float*)d_out;

    cudaFuncSetAttribute(chunk_prep_kernel,
                         cudaFuncAttributeMaxDynamicSharedMemorySize, PREP_SMEM);
    cudaFuncSetAttribute(chunk_out_kernel,
                         cudaFuncAttributeMaxDynamicSharedMemorySize, CO_SMEM);
    cudaFuncSetAttribute(proj_gemm_kernel,
                         cudaFuncAttributeMaxDynamicSharedMemorySize, GSMEM);
    cudaFuncSetAttribute(out_gemm_kernel,
                         cudaFuncAttributeMaxDynamicSharedMemorySize, GSMEM);

    cvt_kernel<<<Mrows * Dd / 2048, 256>>>(x);
    wtrans_kernel<<<dim3(32, 32, 5), 256>>>(Wq, Wk, Wv, Wg, Wo);
    proj_gemm_kernel<<<dim3(INNER / 128, Mrows / 128, 4), 128, GSMEM>>>();
    conv_kernel<<<dim3(Mrows / 8, 4, 3), 128>>>(cq_w, cq_b, ck_w, ck_b,
                                                cv_w, cv_b);   // launch #4
    ab_kernel<<<Mrows / 32, 128>>>(x, Wa, ba, Wb, bb);
    chunk_prep_kernel<<<1024, 256, PREP_SMEM>>>();
    chunk_scan_kernel<<<dim3(Bz * Hh, 4), 256>>>();
    chunk_out_kernel<<<1024, 256, CO_SMEM>>>();
    rmsgate_kernel<<<Mrows, 256>>>(gamma);
    out_gemm_kernel<<<dim3(Dd / 128, Mrows / 128), 128, GSMEM>>>(out);
}

// round 14
// speedup vs baseline: 1.2914x; 1.0287x over previous
#include <cuda_runtime.h>
#include <cuda_fp16.h>
#include <math.h>
#include <stdint.h>

// Problem constants
#define Bz 2
#define Tt 2048
#define Dd 1024
#define Hh 16
#define dh 64
#define INNER 1024
#define Mrows 4096   // B*T
#define NCHUNK 32
#define CP 65        // padded stride for 64x64 smem tiles (SIMT kernels)
#define CO 68        // padded stride for mma tiles

// ---------------- scratch ----------------------------------------------------
__device__ float g_Xq[Mrows * INNER];
__device__ float g_Xk[Mrows * INNER];
__device__ float g_Xv[Mrows * INNER];
__device__ float g_Xg[Mrows * INNER];
__device__ float g_Qn[Mrows * INNER];
__device__ float g_Kn[Mrows * INNER];
__device__ float g_Vv[Mrows * INNER];
__device__ float g_AB[Mrows * 32];
__device__ float g_O [Mrows * INNER];
__device__ __half g_xh[Mrows * Dd];        // fp16 x
__device__ __half g_Wh[5 * Dd * INNER];    // fp16 TRANSPOSED weights [n][k]
__device__ __half g_Yh[Mrows * INNER];     // fp16 rms*gamma*gate
__device__ float g_T [1024 * 4096];
__device__ float g_W [1024 * 4096];
__device__ float g_M [1024 * 4096];
__device__ float g_N [1024 * 4096];
__device__ float g_S0[1024 * 4096];
__device__ float g_gam[1024 * 64];
__device__ float g_r  [1024 * 64];

// ---------------- helpers ----------------------------------------------------
__device__ __forceinline__ unsigned cvt_tf32(float f) {
    unsigned u;
    asm("cvt.rna.tf32.f32 %0, %1;" : "=r"(u) : "f"(f));
    return u;
}
__device__ __forceinline__ float rna_tf32(float f) {
    return __uint_as_float(cvt_tf32(f));
}
__device__ __forceinline__ uint32_t smem_u32(const void* p) {
    uint32_t a;
    asm("{ .reg .u64 t; cvta.to.shared.u64 t, %1; cvt.u32.u64 %0, t; }"
        : "=r"(a) : "l"(p));
    return a;
}
__device__ __forceinline__ void cp16(uint32_t saddr, const void* gptr) {
    asm volatile("cp.async.cg.shared.global [%0], [%1], 16;" :: "r"(saddr), "l"(gptr));
}
#define CP_COMMIT() asm volatile("cp.async.commit_group;" ::: "memory")

__device__ __forceinline__ void mma_tf32(float* d, unsigned a0, unsigned a1,
                                         unsigned a2, unsigned a3,
                                         unsigned b0, unsigned b1) {
    asm("mma.sync.aligned.m16n8k8.row.col.f32.tf32.tf32.f32 "
        "{%0,%1,%2,%3}, {%4,%5,%6,%7}, {%8,%9}, {%0,%1,%2,%3};\n"
        : "+f"(d[0]), "+f"(d[1]), "+f"(d[2]), "+f"(d[3])
        : "r"(a0), "r"(a1), "r"(a2), "r"(a3), "r"(b0), "r"(b1));
}

__device__ __forceinline__ void mma_f16(float* d, unsigned a0, unsigned a1,
                                        unsigned a2, unsigned a3,
                                        unsigned b0, unsigned b1) {
    asm("mma.sync.aligned.m16n8k16.row.col.f32.f16.f16.f32 "
        "{%0,%1,%2,%3}, {%4,%5,%6,%7}, {%8,%9}, {%0,%1,%2,%3};\n"
        : "+f"(d[0]), "+f"(d[1]), "+f"(d[2]), "+f"(d[3])
        : "r"(a0), "r"(a1), "r"(a2), "r"(a3), "r"(b0), "r"(b1));
}

// 64x64x64 tf32 mma block: acc[m][n] += sum_k As_[m][k]*Bs_[n][k], CO stride.
__device__ __forceinline__ void mma_block64(const float* __restrict__ As_,
                                            const float* __restrict__ Bs_,
                                            int m0, int n0, int lane,
                                            float acc[2][2][4])
{
#pragma unroll
    for (int k8 = 0; k8 < 64; k8 += 8) {
        const int kk0 = k8 + (lane & 3);
        const int kk1 = kk0 + 4;
        unsigned af[2][4], bf[2][2];
#pragma unroll
        for (int mt = 0; mt < 2; mt++) {
            const int r0 = m0 + mt * 16 + (lane >> 2);
            af[mt][0] = __float_as_uint(As_[r0 * CO + kk0]);
            af[mt][1] = __float_as_uint(As_[(r0 + 8) * CO + kk0]);
            af[mt][2] = __float_as_uint(As_[r0 * CO + kk1]);
            af[mt][3] = __float_as_uint(As_[(r0 + 8) * CO + kk1]);
        }
#pragma unroll
        for (int nt = 0; nt < 2; nt++) {
            const int n = n0 + nt * 8 + (lane >> 2);
            bf[nt][0] = __float_as_uint(Bs_[n * CO + kk0]);
            bf[nt][1] = __float_as_uint(Bs_[n * CO + kk1]);
        }
#pragma unroll
        for (int mt = 0; mt < 2; mt++)
#pragma unroll
            for (int nt = 0; nt < 2; nt++)
                mma_tf32(acc[mt][nt], af[mt][0], af[mt][1], af[mt][2], af[mt][3],
                         bf[nt][0], bf[nt][1]);
    }
}

// ---------------- fp16 GEMM, 128x128 tile, cp.async 3-stage pipeline ---------
#define PADH 24
#define HST (128 * PADH)
#define GSMEM (6 * HST * 2)

__device__ __forceinline__ void hgemm128(const __half* __restrict__ A,
                                         const __half* __restrict__ Bt,
                                         float* __restrict__ C,
                                         int N, int bm, int bn,
                                         bool do_silu)
{
    extern __shared__ __half smh[];

    const int tid  = threadIdx.x;
    const int lane = tid & 31;
    const int wid  = tid >> 5;
    const int warpM = (wid & 1) * 64;
    const int warpN = (wid >> 1) * 64;

    float acc[4][8][4];
#pragma unroll
    for (int mt = 0; mt < 4; mt++)
#pragma unroll
        for (int nt = 0; nt < 8; nt++)
#pragma unroll
            for (int i = 0; i < 4; i++) acc[mt][nt][i] = 0.f;

    const uint32_t asu = smem_u32(smh);
    const uint32_t bsu = asu + 3 * HST * 2;

    auto load_stage = [&](int kt, int st) {
        const int k0 = kt << 4;
        const uint32_t sa = asu + st * (HST * 2);
        const uint32_t sb = bsu + st * (HST * 2);
#pragma unroll
        for (int i = 0; i < 2; i++) {
            const int idx = tid + i * 128;
            const int row = idx >> 1;
            const int hf  = (idx & 1) * 8;
            cp16(sa + (row * PADH + hf) * 2, A  + (long)(bm + row) * 1024 + k0 + hf);
            cp16(sb + (row * PADH + hf) * 2, Bt + (long)(bn + row) * 1024 + k0 + hf);
        }
        CP_COMMIT();
    };

    load_stage(0, 0);
    load_stage(1, 1);
    load_stage(2, 2);

    const int fr = lane >> 2;
    const int kp = (lane & 3) * 2;

    for (int kt = 0; kt < 64; kt++) {
        const int st = kt - (kt / 3) * 3;
        if (kt <= 61)      asm volatile("cp.async.wait_group 2;" ::: "memory");
        else if (kt == 62) asm volatile("cp.async.wait_group 1;" ::: "memory");
        else               asm volatile("cp.async.wait_group 0;" ::: "memory");
        __syncthreads();

        const __half* as = smh + st * HST;
        const __half* bs = smh + 3 * HST + st * HST;

        unsigned af[4][4], bf[8][2];
#pragma unroll
        for (int mt = 0; mt < 4; mt++) {
            const int r0 = warpM + mt * 16 + fr;
            af[mt][0] = *(const unsigned*)(as + r0 * PADH + kp);
            af[mt][1] = *(const unsigned*)(as + (r0 + 8) * PADH + kp);
            af[mt][2] = *(const unsigned*)(as + r0 * PADH + kp + 8);
            af[mt][3] = *(const unsigned*)(as + (r0 + 8) * PADH + kp + 8);
        }
#pragma unroll
        for (int nt = 0; nt < 8; nt++) {
            const int n = warpN + nt * 8 + fr;
            bf[nt][0] = *(const unsigned*)(bs + n * PADH + kp);
            bf[nt][1] = *(const unsigned*)(bs + n * PADH + kp + 8);
        }
#pragma unroll
        for (int mt = 0; mt < 4; mt++)
#pragma unroll
            for (int nt = 0; nt < 8; nt++)
                mma_f16(acc[mt][nt], af[mt][0], af[mt][1], af[mt][2], af[mt][3],
                        bf[nt][0], bf[nt][1]);

        __syncthreads();
        if (kt + 3 < 64) load_stage(kt + 3, st);
    }

#pragma unroll
    for (int mt = 0; mt < 4; mt++) {
        const int r0 = bm + warpM + mt * 16 + (lane >> 2);
#pragma unroll
        for (int nt = 0; nt < 8; nt++) {
            const int c = bn + warpN + nt * 8 + ((lane & 3) << 1);
            float v0 = acc[mt][nt][0], v1 = acc[mt][nt][1];
            float v2 = acc[mt][nt][2], v3 = acc[mt][nt][3];
            if (do_silu) {
                v0 = v0 / (1.f + expf(-v0));
                v1 = v1 / (1.f + expf(-v1));
                v2 = v2 / (1.f + expf(-v2));
                v3 = v3 / (1.f + expf(-v3));
            }
            *(float2*)(C + (long)r0 * N + c)       = make_float2(v0, v1);
            *(float2*)(C + (long)(r0 + 8) * N + c) = make_float2(v2, v3);
        }
    }
}

__global__ __launch_bounds__(128) void proj_gemm_kernel()
{
    const int z = blockIdx.z;
    const __half* W = g_Wh + (long)z * (Dd * INNER);
    float* O;
    bool silu = false;
    switch (z) {
        case 0:  O = g_Xq; break;
        case 1:  O = g_Xk; break;
        case 2:  O = g_Xv; break;
        default: O = g_Xg; silu = true; break;
    }
    hgemm128(g_xh, W, O, INNER, blockIdx.y * 128, blockIdx.x * 128, silu);
}

__global__ __launch_bounds__(128) void out_gemm_kernel(float* __restrict__ out)
{
    hgemm128(g_Yh, g_Wh + 4L * Dd * INNER, out, Dd,
             blockIdx.y * 128, blockIdx.x * 128, false);
}

// ---------------- W transpose + fp16 -----------------------------------------
__global__ __launch_bounds__(256) void wtrans_kernel(
    const float* __restrict__ Wq, const float* __restrict__ Wk,
    const float* __restrict__ Wv, const float* __restrict__ Wg,
    const float* __restrict__ Wo)
{
    const float* W;
    switch (blockIdx.z) {
        case 0: W = Wq; break;
        case 1: W = Wk; break;
        case 2: W = Wv; break;
        case 3: W = Wg; break;
        default: W = Wo; break;
    }
    __half* Out = g_Wh + (long)blockIdx.z * (Dd * INNER);
    __shared__ float t[32][33];
    const int tx = threadIdx.x & 31;
    const int ty = threadIdx.x >> 5;
    const int bx = blockIdx.x * 32;
    const int by = blockIdx.y * 32;
#pragma unroll
    for (int i = 0; i < 4; i++)
        t[ty + i * 8][tx] = W[(long)(by + ty + i * 8) * 1024 + bx + tx];
    __syncthreads();
#pragma unroll
    for (int i = 0; i < 4; i++)
        Out[(long)(bx + ty + i * 8) * 1024 + by + tx] = __float2half_rn(t[tx][ty + i * 8]);
}

// ---------------- conv (no shared memory — occupancy-unconstrained) ----------
__global__ __launch_bounds__(128) void conv_kernel(
    const float* __restrict__ cq_w, const float* __restrict__ cq_b,
    const float* __restrict__ ck_w, const float* __restrict__ ck_b,
    const float* __restrict__ cv_w, const float* __restrict__ cv_b)
{
    const float* Xin; float* Out; const float* cw; const float* cb; bool donorm;
    switch (blockIdx.z) {
        case 0:  Xin = g_Xq; Out = g_Qn; cw = cq_w; cb = cq_b; donorm = true;  break;
        case 1:  Xin = g_Xk; Out = g_Kn; cw = ck_w; cb = ck_b; donorm = true;  break;
        default: Xin = g_Xv; Out = g_Vv; cw = cv_w; cb = cv_b; donorm = false; break;
    }
    const int bt0 = blockIdx.x * 8;
    const int t0  = bt0 & (Tt - 1);
    const int lane = threadIdx.x & 31;
    const int wid  = threadIdx.x >> 5;
    const int h = blockIdx.y * 4 + wid;
    const int c0 = h * 64 + lane;

    float x0[11], x1[11];
#pragma unroll
    for (int i = 0; i < 11; i++) {
        const int t = t0 - 3 + i;
        if (t < 0) { x0[i] = 0.f; x1[i] = 0.f; }
        else {
            const long g = (long)(bt0 - t0 + t) * INNER + c0;
            x0[i] = Xin[g];
            x1[i] = Xin[g + 32];
        }
    }
    float w0[4], w1[4];
#pragma unroll
    for (int k = 0; k < 4; k++) {
        w0[k] = cw[c0 * 4 + k];
        w1[k] = cw[(c0 + 32) * 4 + k];
    }
    const float b0 = cb[c0], b1 = cb[c0 + 32];

#pragma unroll
    for (int tt = 0; tt < 8; tt++) {
        float a0 = b0, a1 = b1;
#pragma unroll
        for (int k = 0; k < 4; k++) {
            a0 = fmaf(x0[tt + k], w0[k], a0);
            a1 = fmaf(x1[tt + k], w1[k], a1);
        }
        float s0 = a0 / (1.f + expf(-a0));
        float s1 = a1 / (1.f + expf(-a1));
        float ss = s0 * s0 + s1 * s1;
        ss += __shfl_xor_sync(0xffffffffu, ss, 16);
        ss += __shfl_xor_sync(0xffffffffu, ss, 8);
        ss += __shfl_xor_sync(0xffffffffu, ss, 4);
        ss += __shfl_xor_sync(0xffffffffu, ss, 2);
        ss += __shfl_xor_sync(0xffffffffu, ss, 1);
        if (donorm) {
            const float inv = 1.f / fmaxf(sqrtf(ss), 1e-12f);
            s0 *= inv; s1 *= inv;
        }
        const long g = (long)(bt0 + tt) * INNER + c0;
        Out[g] = s0;
        Out[g + 32] = s1;
    }
}

// ---------------- alpha/beta mini-GEMM + x->fp16 conversion ------------------
__global__ __launch_bounds__(128) void ab_kernel(
    const float* __restrict__ x,
    const float* __restrict__ Wa, const float* __restrict__ ba,
    const float* __restrict__ Wb, const float* __restrict__ bb)
{
    __shared__ float s_ab[32 * 65 + 64 * 33];
    const int blk = blockIdx.x;
    const int tid = threadIdx.x;
    float* xs = s_ab;
    float* ws = s_ab + 32 * 65;
    const int mrow = tid >> 2;
    const int ogrp = tid & 3;

    float acc[8];
#pragma unroll
    for (int j = 0; j < 8; j++) acc[j] = 0.f;

    for (int k0 = 0; k0 < Dd; k0 += 64) {
#pragma unroll
        for (int i = 0; i < 4; i++) {
            const int idx = tid + i * 128;
            const int row = idx >> 4;
            const int c4  = (idx & 15) << 2;
            const long goff = (long)(blk * 32 + row) * Dd + k0 + c4;
            float4 v = *(const float4*)(x + goff);
            xs[row * 65 + c4 + 0] = v.x;
            xs[row * 65 + c4 + 1] = v.y;
            xs[row * 65 + c4 + 2] = v.z;
            xs[row * 65 + c4 + 3] = v.w;
            // fused x -> fp16 conversion (replaces cvt_kernel)
            __half2 hh[2];
            hh[0] = __floats2half2_rn(v.x, v.y);
            hh[1] = __floats2half2_rn(v.z, v.w);
            *(uint2*)(g_xh + goff) = *(const uint2*)hh;
        }
#pragma unroll
        for (int i = 0; i < 16; i++) {
            const int idx = tid + i * 128;
            const int row = idx >> 5;
            const int col = idx & 31;
            ws[row * 33 + col] = (col < 16) ? Wa[(k0 + row) * Hh + col]
                                            : Wb[(k0 + row) * Hh + col - 16];
        }
        __syncthreads();
#pragma unroll 8
        for (int k = 0; k < 64; k++) {
            const float xv = xs[mrow * 65 + k];
#pragma unroll
            for (int j = 0; j < 8; j++)
                acc[j] = fmaf(xv, ws[k * 33 + ogrp * 8 + j], acc[j]);
        }
        __syncthreads();
    }
#pragma unroll
    for (int j = 0; j < 8; j++) {
        const int o = ogrp * 8 + j;
        const float bias = (o < 16) ? ba[o] : bb[o - 16];
        g_AB[(long)(blk * 32 + mrow) * 32 + o] =
            1.f / (1.f + expf(-(acc[j] + bias)));
    }
}

// ============== chunked delta-rule scan ======================================
// prep: L + solve in fp32; M,N via tf32 mma (error is decayed by gC ~ 3e-4).
#define PREP_SMEM ((3 * 64 * CP + 3 * 64 * CO + 128) * 4)

__global__ __launch_bounds__(256, 2) void chunk_prep_kernel()
{
    extern __shared__ float sm[];
    float* sK   = sm;                         // [64][CP] raw K
    float* sV   = sm + 64 * CP;               // [64][CP] raw V
    float* sL   = sm + 2 * 64 * CP;           // [64][CP] L
    float* sWT  = sm + 3 * 64 * CP;           // [64][CO] W^T (rounded)
    float* sTT  = sWT + 64 * CO;              // [64][CO] T^T (rounded)
    float* sKsT = sWT + 2 * 64 * CO;          // [64][CO] (gC r K)^T (rounded)
    float* sGam = sWT + 3 * 64 * CO;
    float* sR   = sGam + 64;

    const int chunk = blockIdx.x;
    const int c  = chunk & (NCHUNK - 1);
    const int bh = chunk >> 5;
    const int b = bh >> 4, h = bh & 15;
    const int tid = threadIdx.x;
    const long rowbase = (long)b * Tt + c * 64;
    const int colbase = h * dh;
    const long cb = (long)chunk * 4096;

    for (int idx = tid; idx < 1024; idx += 256) {
        const int row = idx >> 4;
        const int c4  = (idx & 15) << 2;
        const long g = (rowbase + row) * INNER + colbase + c4;
        float4 kv = *(const float4*)(g_Kn + g);
        float4 vv = *(const float4*)(g_Vv + g);
        sK[row * CP + c4 + 0] = kv.x; sK[row * CP + c4 + 1] = kv.y;
        sK[row * CP + c4 + 2] = kv.z; sK[row * CP + c4 + 3] = kv.w;
        sV[row * CP + c4 + 0] = vv.x; sV[row * CP + c4 + 1] = vv.y;
        sV[row * CP + c4 + 2] = vv.z; sV[row * CP + c4 + 3] = vv.w;
    }
    if (tid < 64) {
        sGam[tid] = g_AB[(rowbase + tid) * 32 + h];
        sR[tid]   = g_AB[(rowbase + tid) * 32 + 16 + h];
    }
    __syncthreads();
    if (tid == 0) {
        float p = 1.f;
        for (int i = 0; i < 64; i++) { p *= sGam[i]; sGam[i] = p; }
    }
    __syncthreads();
    if (tid < 64) sR[tid] = sR[tid] / sGam[tid];
    __syncthreads();

    const int ty = tid >> 4, tx = tid & 15;

    // L[j][i] = (i<j) ? gam[j]*r[i]*<k_i,k_j> : 0   (fp32 SIMT)
    {
        float acc[4][4];
#pragma unroll
        for (int v = 0; v < 4; v++)
#pragma unroll
            for (int u = 0; u < 4; u++) acc[v][u] = 0.f;
        for (int k = 0; k < 64; k++) {
            float a[4], bb[4];
#pragma unroll
            for (int v = 0; v < 4; v++) a[v]  = sK[(ty + 16 * v) * CP + k];
#pragma unroll
            for (int u = 0; u < 4; u++) bb[u] = sK[(tx + 16 * u) * CP + k];
#pragma unroll
            for (int v = 0; v < 4; v++)
#pragma unroll
                for (int u = 0; u < 4; u++)
                    acc[v][u] = fmaf(a[v], bb[u], acc[v][u]);
        }
#pragma unroll
        for (int v = 0; v < 4; v++)
#pragma unroll
            for (int u = 0; u < 4; u++) {
                const int j = ty + 16 * v, i = tx + 16 * u;
                sL[j * CP + i] = (i < j) ? acc[v][u] * sGam[j] * sR[i] : 0.f;
            }
        __syncthreads();
    }

    // solve (tid<128, fp32, in registers)  ||  build Ks^T (tid>=128)
    const float gC = sGam[63];
    float rr_[64];
    const int col = tid & 63;
    const int isW = (tid >> 6) & 1;
    if (tid < 128) {
#pragma unroll
        for (int j = 0; j < 64; j++)
            rr_[j] = isW ? sGam[j] * sK[j * CP + col] : sV[j * CP + col];
#pragma unroll
        for (int j = 0; j < 64; j++) {
            const float xj = rr_[j];
#pragma unroll
            for (int i = j + 1; i < 64; i++)
                rr_[i] -= sL[i * CP + j] * xj;
        }
    } else {
        const int t2 = tid - 128;
        for (int idx = t2; idx < 4096; idx += 128) {
            const int j = idx & 63, q = idx >> 6;
            sKsT[q * CO + j] = rna_tf32(gC * sR[j] * sK[j * CP + q]);
        }
    }
    __syncthreads();

    if (tid < 128) {
        float* st   = isW ? sWT : sTT;
        float* gdst = isW ? g_W : g_T;
#pragma unroll
        for (int j = 0; j < 64; j++) {
            st[col * CO + j] = rna_tf32(rr_[j]);
            gdst[cb + j * 64 + col] = rr_[j];
        }
    }
    if (tid < 64) {
        g_gam[chunk * 64 + tid] = sGam[tid];
        g_r  [chunk * 64 + tid] = sR[tid];
    }
    __syncthreads();

    // M = gC*I - W^T Ks;  N = T^T Ks   via tf32 mma
    {
        const int lane = tid & 31;
        const int wid  = tid >> 5;
        const int m0 = (wid & 1) * 32;
        const int n0 = (wid >> 1) * 16;
        float accM[2][2][4], accN[2][2][4];
#pragma unroll
        for (int mt = 0; mt < 2; mt++)
#pragma unroll
            for (int nt = 0; nt < 2; nt++)
#pragma unroll
                for (int i = 0; i < 4; i++) { accM[mt][nt][i] = 0.f; accN[mt][nt][i] = 0.f; }
        mma_block64(sWT, sKsT, m0, n0, lane, accM);
        mma_block64(sTT, sKsT, m0, n0, lane, accN);
#pragma unroll
        for (int mt = 0; mt < 2; mt++) {
            const int p0 = m0 + mt * 16 + (lane >> 2);
#pragma unroll
            for (int nt = 0; nt < 2; nt++) {
                const int q0 = n0 + nt * 8 + ((lane & 3) << 1);
#pragma unroll
                for (int half = 0; half < 2; half++) {
                    const int p = p0 + half * 8;
                    const float m0v = ((p == q0)     ? gC : 0.f) - accM[mt][nt][half * 2 + 0];
                    const float m1v = ((p == q0 + 1) ? gC : 0.f) - accM[mt][nt][half * 2 + 1];
                    *(float2*)(g_M + cb + p * 64 + q0) = make_float2(m0v, m1v);
                    *(float2*)(g_N + cb + p * 64 + q0) =
                        make_float2(accN[mt][nt][half * 2 + 0], accN[mt][nt][half * 2 + 1]);
                }
            }
        }
    }
}

// ---- chunk_scan: cp.async double-buffered M/N prefetch ----------------------
#define SCAN_SMEM ((2 * 4096 + 2 * 1024) * 4)   // 40 KB dynamic

__global__ __launch_bounds__(256) void chunk_scan_kernel()
{
    extern __shared__ float dsm[];
    float* sMb = dsm;               // [2][4096]
    float* sNb = dsm + 2 * 4096;    // [2][1024]
    __shared__ float sS[16 * 64];

    const int bh = blockIdx.x;
    const int R0 = blockIdx.y * 16;
    const int tid = threadIdx.x;
    const int row = tid >> 4;
    const int tx  = tid & 15;
    const uint32_t su = smem_u32(dsm);

    auto issue = [&](int c, int buf) {
        const long cb = (long)(bh * NCHUNK + c) * 4096;
#pragma unroll
        for (int i = 0; i < 4; i++) {
            const int e = tid + i * 256;          // 0..1023 16B-chunks of M
            cp16(su + (buf * 4096 + e * 4) * 4, g_M + cb + e * 4);
        }
        cp16(su + (2 * 4096 + buf * 1024 + tid * 4) * 4,
             g_N + cb + (long)R0 * 64 + tid * 4);
        CP_COMMIT();
    };

    for (int idx = tid; idx < 1024; idx += 256) sS[idx] = 0.f;
    issue(0, 0);
    __syncthreads();

    for (int c = 0; c < NCHUNK; c++) {
        const int buf = c & 1;
        if (c + 1 < NCHUNK) {
            issue(c + 1, buf ^ 1);
            asm volatile("cp.async.wait_group 1;" ::: "memory");
        } else {
            asm volatile("cp.async.wait_group 0;" ::: "memory");
        }
        __syncthreads();

        const long cb = (long)(bh * NCHUNK + c) * 4096;
        for (int idx = tid; idx < 1024; idx += 256)
            g_S0[cb + (long)(R0 + (idx >> 6)) * 64 + (idx & 63)] = sS[idx];

        const float* M  = sMb + buf * 4096;
        const float* Nn = sNb + buf * 1024;
        float acc[4];
#pragma unroll
        for (int u = 0; u < 4; u++)
            acc[u] = Nn[row * 64 + tx + 16 * u];
        for (int k = 0; k < 64; k++) {
            const float s = sS[row * 64 + k];
#pragma unroll
            for (int u = 0; u < 4; u++)
                acc[u] = fmaf(s, M[k * 64 + tx + 16 * u], acc[u]);
        }
        __syncthreads();
#pragma unroll
        for (int u = 0; u < 4; u++) sS[row * 64 + tx + 16 * u] = acc[u];
        __syncthreads();
    }
}

// ---- chunk_out: tensor-core (tf32 mma) version ------------------------------
#define CO_SMEM ((6 * 64 * CO + 128) * 4)

__global__ __launch_bounds__(256, 2) void chunk_out_kernel()
{
    extern __shared__ float sm[];
    float* sQg = sm;
    float* sK  = sm + 64 * CO;
    float* sS0 = sm + 2 * 64 * CO;
    float* sW  = sm + 3 * 64 * CO;
    float* sT  = sm + 4 * 64 * CO;
    float* sA  = sm + 5 * 64 * CO;
    float* sGam = sm + 6 * 64 * CO;
    float* sR   = sGam + 64;
    float* sUT  = sK;

    const int chunk = blockIdx.x;
    const int c  = chunk & (NCHUNK - 1);
    const int bh = chunk >> 5;
    const int b = bh >> 4, h = bh & 15;
    const int tid = threadIdx.x;
    const int lane = tid & 31;
    const int wid  = tid >> 5;
    const int m0 = (wid & 1) * 32;
    const int n0 = (wid >> 1) * 16;
    const long rowbase = (long)b * Tt + c * 64;
    const int colbase = h * dh;
    const long cb = (long)chunk * 4096;

    if (tid < 64) {
        sGam[tid] = g_gam[chunk * 64 + tid];
        sR[tid]   = g_r[chunk * 64 + tid];
    }
    __syncthreads();

    for (int idx = tid; idx < 1024; idx += 256) {
        const int row = idx >> 4;
        const int c4  = (idx & 15) << 2;
        const long g = (rowbase + row) * INNER + colbase + c4;
        float4 qv = *(const float4*)(g_Qn + g);
        float4 kv = *(const float4*)(g_Kn + g);
        const float gm = sGam[row];
        sQg[row * CO + c4 + 0] = rna_tf32(qv.x * gm);
        sQg[row * CO + c4 + 1] = rna_tf32(qv.y * gm);
        sQg[row * CO + c4 + 2] = rna_tf32(qv.z * gm);
        sQg[row * CO + c4 + 3] = rna_tf32(qv.w * gm);
        sK [row * CO + c4 + 0] = rna_tf32(kv.x);
        sK [row * CO + c4 + 1] = rna_tf32(kv.y);
        sK [row * CO + c4 + 2] = rna_tf32(kv.z);
        sK [row * CO + c4 + 3] = rna_tf32(kv.w);
    }
    for (int idx = tid; idx < 4096; idx += 256) {
        const int r = idx >> 6, cc = idx & 63;
        sS0[r * CO + cc] = rna_tf32(g_S0[cb + idx]);
        sW [r * CO + cc] = rna_tf32(g_W[cb + idx]);
        sT [r * CO + cc] = g_T[cb + idx];
    }
    __syncthreads();

    // Phase 1: A = tril(diag(gam) Q K^T diag(r))
    {
        float acc[2][2][4];
#pragma unroll
        for (int mt = 0; mt < 2; mt++)
#pragma unroll
            for (int nt = 0; nt < 2; nt++)
#pragma unroll
                for (int i = 0; i < 4; i++) acc[mt][nt][i] = 0.f;
        mma_block64(sQg, sK, m0, n0, lane, acc);
        __syncthreads();
#pragma unroll
        for (int mt = 0; mt < 2; mt++) {
            const int t0r = m0 + mt * 16 + (lane >> 2);
#pragma unroll
            for (int nt = 0; nt < 2; nt++) {
                const int j0 = n0 + nt * 8 + ((lane & 3) << 1);
#pragma unroll
                for (int half = 0; half < 2; half++) {
                    const int t = t0r + half * 8;
                    const float v0 = acc[mt][nt][half * 2 + 0];
                    const float v1 = acc[mt][nt][half * 2 + 1];
                    sA[t * CO + j0]     = (j0     <= t) ? rna_tf32(v0 * sR[j0])     : 0.f;
                    sA[t * CO + j0 + 1] = (j0 + 1 <= t) ? rna_tf32(v1 * sR[j0 + 1]) : 0.f;
                }
            }
        }
    }

    // Phase 2: UT[a][j] = T[j][a] - (S0 W^T)(a,j)
    {
        float acc[2][2][4];
#pragma unroll
        for (int mt = 0; mt < 2; mt++)
#pragma unroll
            for (int nt = 0; nt < 2; nt++)
#pragma unroll
                for (int i = 0; i < 4; i++) acc[mt][nt][i] = 0.f;
        mma_block64(sS0, sW, m0, n0, lane, acc);
        __syncthreads();
#pragma unroll
        for (int mt = 0; mt < 2; mt++) {
            const int a0 = m0 + mt * 16 + (lane >> 2);
#pragma unroll
            for (int nt = 0; nt < 2; nt++) {
                const int j0 = n0 + nt * 8 + ((lane & 3) << 1);
#pragma unroll
                for (int half = 0; half < 2; half++) {
                    const int a = a0 + half * 8;
                    sUT[a * CO + j0]     = rna_tf32(sT[j0 * CO + a]       - acc[mt][nt][half * 2 + 0]);
                    sUT[a * CO + j0 + 1] = rna_tf32(sT[(j0 + 1) * CO + a] - acc[mt][nt][half * 2 + 1]);
                }
            }
        }
    }
    __syncthreads();

    // Phase 3: O = Qg S0^T + A U
    {
        float acc[2][2][4];
#pragma unroll
        for (int mt = 0; mt < 2; mt++)
#pragma unroll
            for (int nt = 0; nt < 2; nt++)
#pragma unroll
                for (int i = 0; i < 4; i++) acc[mt][nt][i] = 0.f;
        mma_block64(sQg, sS0, m0, n0, lane, acc);
        mma_block64(sA, sUT, m0, n0, lane, acc);
#pragma unroll
        for (int mt = 0; mt < 2; mt++) {
            const int t0r = m0 + mt * 16 + (lane >> 2);
#pragma unroll
            for (int nt = 0; nt < 2; nt++) {
                const int a0 = n0 + nt * 8 + ((lane & 3) << 1);
#pragma unroll
                for (int half = 0; half < 2; half++) {
                    const int t = t0r + half * 8;
                    *(float2*)(g_O + (rowbase + t) * INNER + colbase + a0) =
                        make_float2(acc[mt][nt][half * 2 + 0],
                                    acc[mt][nt][half * 2 + 1]);
                }
            }
        }
    }
}

// ---------------- RMS norm + (1+gamma) + gate -> fp16 ------------------------
__global__ __launch_bounds__(256) void rmsgate_kernel(const float* __restrict__ gamma)
{
    const int m = blockIdx.x;
    const int tid = threadIdx.x;
    const long base = (long)m * INNER + tid * 4;
    float4 xv = *(const float4*)(g_O + base);
    float ss = xv.x * xv.x + xv.y * xv.y + xv.z * xv.z + xv.w * xv.w;
    for (int off = 16; off; off >>= 1) ss += __shfl_xor_sync(0xffffffffu, ss, off);
    __shared__ float red[8];
    if ((tid & 31) == 0) red[tid >> 5] = ss;
    __syncthreads();
    float tot = 0.f;
#pragma unroll
    for (int w = 0; w < 8; w++) tot += red[w];
    const float inv = 1.f / sqrtf(tot * (1.f / (float)INNER) + 1e-6f);
    float4 gv = *(const float4*)(g_Xg + base);
    float4 gm = *(const float4*)(gamma + tid * 4);
    __half2 h[2];
    h[0] = __floats2half2_rn(xv.x * inv * (1.f + gm.x) * gv.x,
                             xv.y * inv * (1.f + gm.y) * gv.y);
    h[1] = __floats2half2_rn(xv.z * inv * (1.f + gm.z) * gv.z,
                             xv.w * inv * (1.f + gm.w) * gv.w);
    *(uint2*)(g_Yh + base) = *(const uint2*)h;
}

// ---------------- launch -----------------------------------------------------
extern "C" void kernel_launch(void* const* d_in, const int* in_sizes, int n_in,
                              void* d_out, int out_size)
{
    const float* x    = (const float*)d_in[0];
    const float* Wq   = (const float*)d_in[1];
    const float* Wk   = (const float*)d_in[2];
    const float* Wv   = (const float*)d_in[3];
    const float* Wa   = (const float*)d_in[4];
    const float* ba   = (const float*)d_in[5];
    const float* Wb   = (const float*)d_in[6];
    const float* bb   = (const float*)d_in[7];
    const float* Wg   = (const float*)d_in[8];
    const float* Wo   = (const float*)d_in[9];
    const float* cq_w = (const float*)d_in[10];
    const float* cq_b = (const float*)d_in[11];
    const float* ck_w = (const float*)d_in[12];
    const float* ck_b = (const float*)d_in[13];
    const float* cv_w = (const float*)d_in[14];
    const float* cv_b = (const float*)d_in[15];
    const float* gamma= (const float*)d_in[16];
    float* out = (float*)d_out;

    cudaFuncSetAttribute(chunk_prep_kernel,
                         cudaFuncAttributeMaxDynamicSharedMemorySize, PREP_SMEM);
    cudaFuncSetAttribute(chunk_out_kernel,
                         cudaFuncAttributeMaxDynamicSharedMemorySize, CO_SMEM);
    cudaFuncSetAttribute(proj_gemm_kernel,
                         cudaFuncAttributeMaxDynamicSharedMemorySize, GSMEM);
    cudaFuncSetAttribute(out_gemm_kernel,
                         cudaFuncAttributeMaxDynamicSharedMemorySize, GSMEM);

    wtrans_kernel<<<dim3(32, 32, 5), 256>>>(Wq, Wk, Wv, Wg, Wo);
    ab_kernel<<<Mrows / 32, 128>>>(x, Wa, ba, Wb, bb);   // also writes g_xh
    proj_gemm_kernel<<<dim3(INNER / 128, Mrows / 128, 4), 128, GSMEM>>>();
    conv_kernel<<<dim3(Mrows / 8, 4, 3), 128>>>(cq_w, cq_b, ck_w, ck_b,
                                                cv_w, cv_b);   // launch #4
    chunk_prep_kernel<<<1024, 256, PREP_SMEM>>>();
    chunk_scan_kernel<<<dim3(Bz * Hh, 4), 256, SCAN_SMEM>>>();
    chunk_out_kernel<<<1024, 256, CO_SMEM>>>();
    rmsgate_kernel<<<Mrows, 256>>>(gamma);
    out_gemm_kernel<<<dim3(Dd / 128, Mrows / 128), 128, GSMEM>>>(out);
}